// round 12
// baseline (speedup 1.0000x reference)
#include <cuda_runtime.h>
#include <math.h>

#define BB   4
#define SS   64
#define DDIM 512
#define HH   8
#define DH   64
#define DFF  2048
#define LLAY 2
#define VV   32128
#define TT   16
#define NEGV (-1e9f)

#define GF_RES  1
#define GF_RELU 2

#define NB 148
#define NT 512

// ---------------- scratch (device globals; no allocations) ----------------
__device__ float g_x  [BB*SS*DDIM];
__device__ float g_h  [BB*SS*DDIM];
__device__ float g_q  [BB*SS*DDIM];
__device__ float g_k  [BB*SS*DDIM];
__device__ float g_v  [BB*SS*DDIM];
__device__ float g_at [BB*SS*DDIM];
__device__ float g_ff [BB*SS*DFF];
__device__ float g_hs [BB*SS*DDIM];
__device__ float g_ckc[LLAY*BB*SS*DDIM];
__device__ float g_cvc[LLAY*BB*SS*DDIM];
__device__ float g_skc[LLAY*BB*TT*DDIM];
__device__ float g_svc[LLAY*BB*TT*DDIM];
__device__ float g_xd [BB*DDIM];
__device__ float g_qd [BB*DDIM];
__device__ float g_ad [BB*DDIM];
__device__ float g_fd [BB*DFF];
__device__ float g_logits[BB*VV];
__device__ float g_part[1048576];
// decode k-split partial buffers: [kb(4)][m(4)][512]
__device__ float g_p3[16*DDIM];
__device__ float g_p4[16*DDIM];
__device__ float g_p6[16*DDIM];
__device__ float g_p8[16*DDIM];

__device__ unsigned g_barcnt = 0;
__device__ unsigned g_bargen = 0;

// ======================= encoder kernels =======================
__global__ void embed_kernel(const int* __restrict__ ids, const float* __restrict__ emb) {
    int row = blockIdx.x;
    int id  = ids[row];
    for (int d = threadIdx.x; d < DDIM; d += 256)
        g_x[row*DDIM + d] = emb[(size_t)id*DDIM + d];
}

__global__ void rmsnorm_kernel(const float* __restrict__ x, const float* __restrict__ w,
                               float* __restrict__ o) {
    int r = blockIdx.x, tid = threadIdx.x;
    __shared__ float red[256];
    float a = x[r*DDIM + tid];
    float b = x[r*DDIM + 256 + tid];
    red[tid] = a*a + b*b;
    __syncthreads();
    for (int s = 128; s > 0; s >>= 1) { if (tid < s) red[tid] += red[tid+s]; __syncthreads(); }
    float inv = rsqrtf(red[0] / (float)DDIM + 1e-6f);
    o[r*DDIM + tid]       = a * inv * w[tid];
    o[r*DDIM + 256 + tid] = b * inv * w[256 + tid];
}

__global__ void gemm_split(const float* __restrict__ A, const float* __restrict__ W,
                           float* __restrict__ part, int M, int N, int K, int KS) {
    __shared__ float As[16][64];
    __shared__ float Bs[16][64];
    int row0 = blockIdx.y * 64, col0 = blockIdx.x * 64;
    int ksid = blockIdx.z;
    int kc = K / KS;
    int kbeg = ksid * kc, kend = kbeg + kc;
    int tid = threadIdx.x;
    int ty = tid / 16, tx = tid % 16;
    float acc[4][4];
    #pragma unroll
    for (int i = 0; i < 4; i++)
        #pragma unroll
        for (int j = 0; j < 4; j++) acc[i][j] = 0.f;

    for (int k0 = kbeg; k0 < kend; k0 += 16) {
        #pragma unroll
        for (int p = 0; p < 4; p++) {
            int i = tid + p*256;
            int r = i >> 4, c = i & 15;
            As[c][r] = A[(row0 + r)*K + k0 + c];
        }
        #pragma unroll
        for (int p = 0; p < 4; p++) {
            int i = tid + p*256;
            int r = i >> 6, c = i & 63;
            Bs[r][c] = W[(size_t)(k0 + r)*N + col0 + c];
        }
        __syncthreads();
        #pragma unroll
        for (int k = 0; k < 16; k++) {
            float a[4], b[4];
            #pragma unroll
            for (int i = 0; i < 4; i++) a[i] = As[k][ty*4 + i];
            #pragma unroll
            for (int j = 0; j < 4; j++) b[j] = Bs[k][tx*4 + j];
            #pragma unroll
            for (int i = 0; i < 4; i++)
                #pragma unroll
                for (int j = 0; j < 4; j++) acc[i][j] += a[i]*b[j];
        }
        __syncthreads();
    }
    float* pc = part + (size_t)ksid * M * N;
    #pragma unroll
    for (int i = 0; i < 4; i++) {
        int r = row0 + ty*4 + i;
        #pragma unroll
        for (int j = 0; j < 4; j++)
            pc[(size_t)r*N + col0 + tx*4 + j] = acc[i][j];
    }
}

__global__ void gemm_reduce(const float* __restrict__ part, const float* __restrict__ res,
                            float* __restrict__ C, int MN, int KS, int flags) {
    int i = (blockIdx.x*256 + threadIdx.x) * 4;
    if (i >= MN) return;
    float4 s = *(const float4*)(part + i);
    for (int k = 1; k < KS; k++) {
        float4 p = *(const float4*)(part + (size_t)k*MN + i);
        s.x += p.x; s.y += p.y; s.z += p.z; s.w += p.w;
    }
    if (flags & GF_RES) {
        float4 r = *(const float4*)(res + i);
        s.x += r.x; s.y += r.y; s.z += r.z; s.w += r.w;
    }
    if (flags & GF_RELU) {
        s.x = fmaxf(s.x, 0.f); s.y = fmaxf(s.y, 0.f);
        s.z = fmaxf(s.z, 0.f); s.w = fmaxf(s.w, 0.f);
    }
    *(float4*)(C + i) = s;
}

__global__ void enc_attn(const float* __restrict__ Q, const float* __restrict__ K,
                         const float* __restrict__ V, const float* __restrict__ mask,
                         float* __restrict__ O) {
    int bh = blockIdx.x; int b = bh >> 3, h = bh & 7;
    int tid = threadIdx.x;
    __shared__ float Ks[64*65], Vs[64*65], sc[64], se[64];
    for (int i = tid; i < 4096; i += 64) {
        int r = i >> 6, c = i & 63;
        Ks[r*65 + c] = K[(size_t)(b*SS + r)*DDIM + h*DH + c];
        Vs[r*65 + c] = V[(size_t)(b*SS + r)*DDIM + h*DH + c];
    }
    __syncthreads();
    float bias = (1.f - mask[b*SS + tid]) * NEGV;
    for (int q = 0; q < SS; q++) {
        const float* qr = &Q[(size_t)(b*SS + q)*DDIM + h*DH];
        float s = 0.f;
        #pragma unroll 8
        for (int d = 0; d < DH; d++) s += qr[d]*Ks[tid*65 + d];
        sc[tid] = s * 0.125f + bias;
        __syncthreads();
        float mx = -1e30f;
        for (int j = 0; j < 64; j++) mx = fmaxf(mx, sc[j]);
        se[tid] = expf(sc[tid] - mx);
        __syncthreads();
        float den = 0.f;
        for (int j = 0; j < 64; j++) den += se[j];
        float o = 0.f;
        #pragma unroll 8
        for (int j = 0; j < 64; j++) o += se[j]*Vs[j*65 + tid];
        O[(size_t)(b*SS + q)*DDIM + h*DH + tid] = o / den;
        __syncthreads();
    }
}

// ======================= decode megakernel =======================
__shared__ float  s_xs[4*DFF];     // 32KB   activations [m][k]
__shared__ float4 s_xt[DDIM];      // 8KB
__shared__ float  s_red[1104];
__shared__ float  s_sinv[4];
__shared__ float  s_sc[64];
__shared__ float  s_se[64];
__shared__ float  s_q [64];

__device__ __forceinline__ void gridbar() {
    __syncthreads();
    if (threadIdx.x == 0) {
        __threadfence();
        unsigned my = *(volatile unsigned*)&g_bargen;
        unsigned a = atomicAdd(&g_barcnt, 1u);
        if (a == gridDim.x - 1) {
            atomicExch(&g_barcnt, 0u);
            __threadfence();
            *(volatile unsigned*)&g_bargen = my + 1u;
        } else {
            while (*(volatile unsigned*)&g_bargen == my) { }
            __threadfence();
        }
    }
    __syncthreads();
}

// K=512 prep with optional partial-sum input P[kb(4)][m(4)][512] added to base x.
__device__ __forceinline__ void prep512p(const float* __restrict__ x,
                                         const float* __restrict__ P,
                                         const float* __restrict__ ln, bool xt) {
    int tid = threadIdx.x, lane = tid & 31, w = tid >> 5;
    float v0 = x[tid], v1 = x[512 + tid], v2 = x[1024 + tid], v3 = x[1536 + tid];
    if (P) {
        #pragma unroll
        for (int kb = 0; kb < 4; kb++) {
            v0 += P[(kb*4+0)*512 + tid];
            v1 += P[(kb*4+1)*512 + tid];
            v2 += P[(kb*4+2)*512 + tid];
            v3 += P[(kb*4+3)*512 + tid];
        }
    }
    if (ln) {
        float s0 = v0*v0, s1 = v1*v1, s2 = v2*v2, s3 = v3*v3;
        #pragma unroll
        for (int off = 16; off > 0; off >>= 1) {
            s0 += __shfl_xor_sync(0xffffffffu, s0, off);
            s1 += __shfl_xor_sync(0xffffffffu, s1, off);
            s2 += __shfl_xor_sync(0xffffffffu, s2, off);
            s3 += __shfl_xor_sync(0xffffffffu, s3, off);
        }
        if (lane == 0) {
            s_red[w] = s0; s_red[16 + w] = s1; s_red[32 + w] = s2; s_red[48 + w] = s3;
        }
        float lw = ln[tid];
        v0 *= lw; v1 *= lw; v2 *= lw; v3 *= lw;
    }
    s_xs[tid] = v0; s_xs[512 + tid] = v1; s_xs[1024 + tid] = v2; s_xs[1536 + tid] = v3;
    if (xt) s_xt[tid] = make_float4(v0, v1, v2, v3);
    __syncthreads();
    if (ln && tid < 4) {
        float s = 0.f;
        #pragma unroll
        for (int ww = 0; ww < 16; ww++) s += s_red[tid*16 + ww];
        s_sinv[tid] = rsqrtf(s / 512.0f + 1e-6f);
    }
    __syncthreads();
}

// materialize x (residual stream): g_xd[m] += sum of partials
__device__ __forceinline__ void materialize_x(const float* __restrict__ P, int m) {
    int tid = threadIdx.x;
    float v = g_xd[m*512 + tid];
    #pragma unroll
    for (int kb = 0; kb < 4; kb++) v += P[(kb*4+m)*512 + tid];
    g_xd[m*512 + tid] = v;
}

// K=2048 relu prep
__device__ __forceinline__ void prep_relu2048(const float* __restrict__ x) {
    const float4* xf = (const float4*)x;
    float4* sf = (float4*)s_xs;
    #pragma unroll
    for (int i = threadIdx.x; i < 2048; i += NT) {
        float4 p = xf[i];
        p.x = fmaxf(p.x, 0.f); p.y = fmaxf(p.y, 0.f);
        p.z = fmaxf(p.z, 0.f); p.w = fmaxf(p.w, 0.f);
        sf[i] = p;
    }
    __syncthreads();
}

// direct gemv tile (full K in one block)
template<int K>
__device__ __forceinline__ void gemv_tile(const float* __restrict__ W, int N, int tile,
                                          float* __restrict__ dst, int mstride,
                                          bool use_sinv) {
    constexpr int KC = K / 32;
    int tid = threadIdx.x;
    int w = tid >> 5, lane = tid & 31;
    int sub = lane >> 4, c = lane & 15;
    int ks = w*2 + sub;
    int col = tile*16 + c;
    const float* xp = s_xs + ks*KC;
    const float* wp = W + (size_t)(ks*KC)*N + col;
    float a0=0.f, a1=0.f, a2=0.f, a3=0.f;
    for (int k0 = 0; k0 < KC; k0 += 16) {
        #pragma unroll
        for (int k = 0; k < 16; k++) {
            float wv = wp[(size_t)(k0+k)*N];
            a0 += xp[k0+k]*wv; a1 += xp[K+k0+k]*wv;
            a2 += xp[2*K+k0+k]*wv; a3 += xp[3*K+k0+k]*wv;
        }
    }
    a0 += __shfl_xor_sync(0xffffffffu, a0, 16);
    a1 += __shfl_xor_sync(0xffffffffu, a1, 16);
    a2 += __shfl_xor_sync(0xffffffffu, a2, 16);
    a3 += __shfl_xor_sync(0xffffffffu, a3, 16);
    if (sub == 0) {
        s_red[(c*4+0)*17 + w] = a0;
        s_red[(c*4+1)*17 + w] = a1;
        s_red[(c*4+2)*17 + w] = a2;
        s_red[(c*4+3)*17 + w] = a3;
    }
    __syncthreads();
    if (tid < 64) {
        float s = 0.f;
        #pragma unroll
        for (int w2 = 0; w2 < 16; w2++) s += s_red[tid*17 + w2];
        int cc = tid >> 2, m = tid & 3;
        int oc = tile*16 + cc;
        if (use_sinv) s *= s_sinv[m];
        dst[(size_t)m*mstride + oc] = s;
    }
    __syncthreads();
}

// k-split gemv: block handles (tile, kb); writes partial (sinv applied, no res)
template<int K, int KSB>
__device__ __forceinline__ void gemv_part(const float* __restrict__ W, int N, int tile, int kb,
                                          float* __restrict__ P, bool use_sinv) {
    constexpr int KB = K / KSB;
    constexpr int KC = KB / 32;
    int tid = threadIdx.x;
    int w = tid >> 5, lane = tid & 31;
    int sub = lane >> 4, c = lane & 15;
    int ks = w*2 + sub;
    int col = tile*16 + c;
    int row0 = kb*KB + ks*KC;
    const float* xp = s_xs + row0;
    const float* wp = W + (size_t)row0*N + col;
    float a0=0.f, a1=0.f, a2=0.f, a3=0.f;
    #pragma unroll
    for (int k = 0; k < KC; k++) {
        float wv = wp[(size_t)k*N];
        a0 += xp[k]*wv; a1 += xp[K+k]*wv; a2 += xp[2*K+k]*wv; a3 += xp[3*K+k]*wv;
    }
    a0 += __shfl_xor_sync(0xffffffffu, a0, 16);
    a1 += __shfl_xor_sync(0xffffffffu, a1, 16);
    a2 += __shfl_xor_sync(0xffffffffu, a2, 16);
    a3 += __shfl_xor_sync(0xffffffffu, a3, 16);
    if (sub == 0) {
        s_red[(c*4+0)*17 + w] = a0;
        s_red[(c*4+1)*17 + w] = a1;
        s_red[(c*4+2)*17 + w] = a2;
        s_red[(c*4+3)*17 + w] = a3;
    }
    __syncthreads();
    if (tid < 64) {
        float s = 0.f;
        #pragma unroll
        for (int w2 = 0; w2 < 16; w2++) s += s_red[tid*17 + w2];
        int cc = tid >> 2, m = tid & 3;
        int oc = tile*16 + cc;
        if (use_sinv) s *= s_sinv[m];
        P[(size_t)(kb*4+m)*N + oc] = s;
    }
    __syncthreads();
}

// warp-per-tile logits
__device__ __forceinline__ void logits_warp(const float* __restrict__ lm,
                                            float* __restrict__ dst) {
    int lane = threadIdx.x & 31;
    int gw = blockIdx.x * (NT/32) + (threadIdx.x >> 5);
    float si0 = s_sinv[0], si1 = s_sinv[1], si2 = s_sinv[2], si3 = s_sinv[3];
    int sub = lane >> 4, c = lane & 15;
    const int NTILE = VV / 16;
    for (int tile = gw; tile < NTILE; tile += NB*(NT/32)) {
        int col = tile*16 + c;
        const float4* xp = s_xt + sub*256;
        const float*  wp = lm + (size_t)(sub*256)*VV + col;
        float a0=0.f, a1=0.f, a2=0.f, a3=0.f;
        for (int k0 = 0; k0 < 256; k0 += 16) {
            #pragma unroll
            for (int k = 0; k < 16; k++) {
                float4 x4 = xp[k0+k];
                float wv = wp[(size_t)(k0+k)*VV];
                a0 += x4.x*wv; a1 += x4.y*wv; a2 += x4.z*wv; a3 += x4.w*wv;
            }
        }
        a0 += __shfl_xor_sync(0xffffffffu, a0, 16);
        a1 += __shfl_xor_sync(0xffffffffu, a1, 16);
        a2 += __shfl_xor_sync(0xffffffffu, a2, 16);
        a3 += __shfl_xor_sync(0xffffffffu, a3, 16);
        if (sub == 0) {
            dst[(size_t)0*VV + col] = a0*si0;
            dst[(size_t)1*VV + col] = a1*si1;
            dst[(size_t)2*VV + col] = a2*si2;
            dst[(size_t)3*VV + col] = a3*si3;
        }
    }
}

__global__ void __launch_bounds__(NT, 1)
decode_megakernel(const float* __restrict__ mask, const float* __restrict__ emb,
                  const float* __restrict__ sq, const float* __restrict__ sk,
                  const float* __restrict__ sv, const float* __restrict__ so,
                  const float* __restrict__ ln1, const float* __restrict__ cq,
                  const float* __restrict__ co, const float* __restrict__ ln2,
                  const float* __restrict__ w1, const float* __restrict__ w2,
                  const float* __restrict__ ln3, const float* __restrict__ lnf,
                  const float* __restrict__ lm, float* __restrict__ out) {
    const size_t DD2 = (size_t)DDIM*DDIM;
    const size_t DF  = (size_t)DDIM*DFF;
    int tid = threadIdx.x;
    int bid = blockIdx.x;

    if (bid < 4)
        g_xd[bid*DDIM + tid] = emb[tid];
    gridbar();

    for (int t = 0; t < TT; t++) {
        for (int l = 0; l < LLAY; l++) {
            // ---- S1: rms(ln1) + QKV (96 direct tiles). base x: l==0 complete; l==1 += P8 ----
            if (bid < 96) {
                prep512p(g_xd, (l == 1) ? g_p8 : nullptr, ln1 + l*DDIM, false);
                int seg = bid >> 5, ti = bid & 31;
                if (seg == 0) {
                    gemv_tile<DDIM>(sq + l*DD2, DDIM, ti, g_qd, DDIM, true);
                } else if (seg == 1) {
                    gemv_tile<DDIM>(sk + l*DD2, DDIM, ti,
                                    g_skc + (size_t)(l*BB*TT + t)*DDIM, TT*DDIM, true);
                } else {
                    gemv_tile<DDIM>(sv + l*DD2, DDIM, ti,
                                    g_svc + (size_t)(l*BB*TT + t)*DDIM, TT*DDIM, true);
                }
            }
            gridbar();

            // ---- S2: self-attention; l==1: blocks 32-35 materialize x += P8 ----
            if (bid < 32) {
                int b = bid >> 3, h = bid & 7;
                int nk = t + 1;
                const float* q = g_qd + b*DDIM + h*DH;
                if (tid < nk) {
                    const float* kr = g_skc + (size_t)((l*BB + b)*TT + tid)*DDIM + h*DH;
                    float s = 0.f;
                    #pragma unroll 16
                    for (int d = 0; d < DH; d++) s += q[d]*kr[d];
                    s_sc[tid] = s * 0.125f;
                }
                __syncthreads();
                if (tid < nk) {
                    float mx = -1e30f;
                    for (int j = 0; j < nk; j++) mx = fmaxf(mx, s_sc[j]);
                    s_se[tid] = expf(s_sc[tid] - mx);
                }
                __syncthreads();
                if (tid < 64) {
                    float den = 0.f, o = 0.f;
                    for (int j = 0; j < nk; j++) {
                        den += s_se[j];
                        o += s_se[j]*g_svc[(size_t)((l*BB + b)*TT + j)*DDIM + h*DH + tid];
                    }
                    g_ad[b*DDIM + h*DH + tid] = o / den;
                }
            } else if (l == 1 && bid < 36) {
                materialize_x(g_p8, bid - 32);
            }
            gridbar();

            // ---- S3: O-proj partials (128 units) ----
            if (bid < 128) {
                prep512p(g_ad, nullptr, nullptr, false);
                gemv_part<DDIM, 4>(so + l*DD2, DDIM, bid & 31, bid >> 5, g_p3, false);
            }
            gridbar();

            // ---- S4: rms(ln2) over x+P3 -> cross-Q partials (128 units) ----
            if (bid < 128) {
                prep512p(g_xd, g_p3, ln2 + l*DDIM, false);
                gemv_part<DDIM, 4>(cq + l*DD2, DDIM, bid & 31, bid >> 5, g_p4, true);
            }
            gridbar();

            // ---- S5: cross-attention (q = sum P4); blocks 32-35 materialize x += P3 ----
            if (bid < 32) {
                int b = bid >> 3, h = bid & 7;
                if (tid < 64) {
                    float qq = 0.f;
                    #pragma unroll
                    for (int kb = 0; kb < 4; kb++)
                        qq += g_p4[(kb*4+b)*DDIM + h*DH + tid];
                    s_q[tid] = qq;
                }
                __syncthreads();
                if (tid < 64) {
                    const float* kr = g_ckc + (size_t)((l*BB + b)*SS + tid)*DDIM + h*DH;
                    float s = 0.f;
                    #pragma unroll 16
                    for (int d = 0; d < DH; d++) s += s_q[d]*kr[d];
                    s_sc[tid] = s * 0.125f + (1.f - mask[b*SS + tid]) * NEGV;
                }
                __syncthreads();
                if (tid < 64) {
                    float mx = -1e30f;
                    for (int j = 0; j < 64; j++) mx = fmaxf(mx, s_sc[j]);
                    s_se[tid] = expf(s_sc[tid] - mx);
                }
                __syncthreads();
                if (tid < 64) {
                    float den = 0.f, o = 0.f;
                    #pragma unroll 8
                    for (int j = 0; j < 64; j++) {
                        den += s_se[j];
                        o += s_se[j]*g_cvc[(size_t)((l*BB + b)*SS + j)*DDIM + h*DH + tid];
                    }
                    g_ad[b*DDIM + h*DH + tid] = o / den;
                }
            } else if (bid >= 32 && bid < 36) {
                materialize_x(g_p3, bid - 32);
            }
            gridbar();

            // ---- S6: cross O-proj partials (128 units) ----
            if (bid < 128) {
                prep512p(g_ad, nullptr, nullptr, false);
                gemv_part<DDIM, 4>(co + l*DD2, DDIM, bid & 31, bid >> 5, g_p6, false);
            }
            gridbar();

            // ---- S7: rms(ln3) over x+P6 -> W1 direct (128 tiles) ----
            if (bid < 128) {
                prep512p(g_xd, g_p6, ln3 + l*DDIM, false);
                gemv_tile<DDIM>(w1 + l*DF, DFF, bid, g_fd, DFF, true);
            }
            gridbar();

            // ---- S8: relu + W2 partials (128 units); blocks 128-131 materialize x += P6 ----
            if (bid < 128) {
                prep_relu2048(g_fd);
                gemv_part<DFF, 4>(w2 + l*DF, DDIM, bid & 31, bid >> 5, g_p8, false);
            } else if (bid < 132) {
                materialize_x(g_p6, bid - 128);
            }
            gridbar();
        }

        // ---- logits: rms(lnf) over x+P8 (all blocks), warp-per-tile ----
        prep512p(g_xd, g_p8, lnf, true);
        logits_warp(lm, g_logits);
        gridbar();

        // ---- softmax + argmax + write probs/pred + zero x_dec ----
        if (bid < 4) {
            int b = bid;
            const float* lg = g_logits + (size_t)b*VV;
            int* sidx = (int*)s_xs;
            float mx = -1e30f; int mi = 0;
            #pragma unroll 4
            for (int v = tid; v < VV; v += NT) {
                float f = lg[v];
                if (f > mx) { mx = f; mi = v; }
            }
            s_red[tid] = mx; sidx[tid] = mi;
            __syncthreads();
            for (int s = 256; s > 0; s >>= 1) {
                if (tid < s) {
                    float o = s_red[tid + s]; int oi = sidx[tid + s];
                    if (o > s_red[tid] || (o == s_red[tid] && oi < sidx[tid])) {
                        s_red[tid] = o; sidx[tid] = oi;
                    }
                }
                __syncthreads();
            }
            float M = s_red[0]; int am = sidx[0];
            __syncthreads();
            float sum = 0.f;
            #pragma unroll 4
            for (int v = tid; v < VV; v += NT) sum += expf(lg[v] - M);
            s_red[tid] = sum;
            __syncthreads();
            for (int s = 256; s > 0; s >>= 1) { if (tid < s) s_red[tid] += s_red[tid + s]; __syncthreads(); }
            float inv = 1.f / s_red[0];
            float* pr = out + (size_t)(b*TT + t)*VV;
            #pragma unroll 4
            for (int v = tid; v < VV; v += NT) pr[v] = expf(lg[v] - M) * inv;
            if (tid == 0)
                out[(size_t)BB*TT*VV + b*TT + t] = (am == 0) ? 1.0f : 0.0f;
            g_xd[b*DDIM + tid] = 0.f;
        }
        gridbar();

        // ---- soft embedding: g_xd += probs @ emb ----
        if (t + 1 < TT) {
            float a0=0.f, a1=0.f, a2=0.f, a3=0.f;
            int d = tid;
            for (int t0 = bid; t0 < VV/128; t0 += gridDim.x) {
                int v0 = t0*128;
                __syncthreads();
                {
                    int m = tid >> 7, j = tid & 127;
                    s_red[m*128 + j] = out[(size_t)(m*TT + t)*VV + v0 + j];
                }
                __syncthreads();
                for (int j0 = 0; j0 < 128; j0 += 16) {
                    #pragma unroll
                    for (int j = 0; j < 16; j++) {
                        float e = emb[(size_t)(v0 + j0 + j)*DDIM + d];
                        a0 += s_red[j0+j]*e;     a1 += s_red[128+j0+j]*e;
                        a2 += s_red[256+j0+j]*e; a3 += s_red[384+j0+j]*e;
                    }
                }
            }
            atomicAdd(&g_xd[0*DDIM + d], a0);
            atomicAdd(&g_xd[1*DDIM + d], a1);
            atomicAdd(&g_xd[2*DDIM + d], a2);
            atomicAdd(&g_xd[3*DDIM + d], a3);
            gridbar();
        }
    }
}

// ---------------- launcher ----------------
extern "C" void kernel_launch(void* const* d_in, const int* in_sizes, int n_in,
                              void* d_out, int out_size) {
    const int*   ids     = (const int*)  d_in[0];
    const float* mask    = (const float*)d_in[1];
    const float* emb     = (const float*)d_in[2];
    const float* enc_wq  = (const float*)d_in[3];
    const float* enc_wk  = (const float*)d_in[4];
    const float* enc_wv  = (const float*)d_in[5];
    const float* enc_wo  = (const float*)d_in[6];
    const float* enc_ln1 = (const float*)d_in[7];
    const float* enc_w1  = (const float*)d_in[8];
    const float* enc_w2  = (const float*)d_in[9];
    const float* enc_ln2 = (const float*)d_in[10];
    const float* enc_lnf = (const float*)d_in[11];
    const float* dec_sq  = (const float*)d_in[12];
    const float* dec_sk  = (const float*)d_in[13];
    const float* dec_sv  = (const float*)d_in[14];
    const float* dec_so  = (const float*)d_in[15];
    const float* dec_ln1 = (const float*)d_in[16];
    const float* dec_cq  = (const float*)d_in[17];
    const float* dec_ck  = (const float*)d_in[18];
    const float* dec_cv  = (const float*)d_in[19];
    const float* dec_co  = (const float*)d_in[20];
    const float* dec_ln2 = (const float*)d_in[21];
    const float* dec_w1  = (const float*)d_in[22];
    const float* dec_w2  = (const float*)d_in[23];
    const float* dec_ln3 = (const float*)d_in[24];
    const float* dec_lnf = (const float*)d_in[25];
    const float* lm      = (const float*)d_in[26];
    float* out = (float*)d_out;

    float *gx, *gh, *gq, *gk, *gv, *gat, *gff, *ghs, *gckc, *gcvc, *gpart;
    cudaGetSymbolAddress((void**)&gx,   g_x);
    cudaGetSymbolAddress((void**)&gh,   g_h);
    cudaGetSymbolAddress((void**)&gq,   g_q);
    cudaGetSymbolAddress((void**)&gk,   g_k);
    cudaGetSymbolAddress((void**)&gv,   g_v);
    cudaGetSymbolAddress((void**)&gat,  g_at);
    cudaGetSymbolAddress((void**)&gff,  g_ff);
    cudaGetSymbolAddress((void**)&ghs,  g_hs);
    cudaGetSymbolAddress((void**)&gckc, g_ckc);
    cudaGetSymbolAddress((void**)&gcvc, g_cvc);
    cudaGetSymbolAddress((void**)&gpart, g_part);

    const int MROWS = BB*SS;
    const size_t DD2 = (size_t)DDIM*DDIM;
    const size_t DF  = (size_t)DDIM*DFF;
    const int MN_DD = MROWS*DDIM;
    const int MN_DF = MROWS*DFF;

    #define GEMM_DD(A, W, RES, C, FLAGS) do {                                          \
        gemm_split<<<dim3(DDIM/64, MROWS/64, 8), 256>>>(A, W, gpart, MROWS, DDIM, DDIM, 8); \
        gemm_reduce<<<MN_DD/1024, 256>>>(gpart, RES, C, MN_DD, 8, FLAGS);              \
    } while (0)

    // ===== encoder =====
    embed_kernel<<<MROWS, 256>>>(ids, emb);
    for (int l = 0; l < LLAY; l++) {
        rmsnorm_kernel<<<MROWS, 256>>>(gx, enc_ln1 + l*DDIM, gh);
        GEMM_DD(gh, enc_wq + l*DD2, nullptr, gq, 0);
        GEMM_DD(gh, enc_wk + l*DD2, nullptr, gk, 0);
        GEMM_DD(gh, enc_wv + l*DD2, nullptr, gv, 0);
        enc_attn<<<BB*HH, 64>>>(gq, gk, gv, mask, gat);
        GEMM_DD(gat, enc_wo + l*DD2, gx, gx, GF_RES);
        rmsnorm_kernel<<<MROWS, 256>>>(gx, enc_ln2 + l*DDIM, gh);
        gemm_split<<<dim3(DFF/64, MROWS/64, 2), 256>>>(gh, enc_w1 + l*DF, gpart, MROWS, DFF, DDIM, 2);
        gemm_reduce<<<MN_DF/1024, 256>>>(gpart, nullptr, gff, MN_DF, 2, GF_RELU);
        gemm_split<<<dim3(DDIM/64, MROWS/64, 8), 256>>>(gff, enc_w2 + l*DF, gpart, MROWS, DDIM, DFF, 8);
        gemm_reduce<<<MN_DD/1024, 256>>>(gpart, gx, gx, MN_DD, 8, GF_RES);
    }
    rmsnorm_kernel<<<MROWS, 256>>>(gx, enc_lnf, ghs);

    // cross K/V precompute
    for (int l = 0; l < LLAY; l++) {
        GEMM_DD(ghs, dec_ck + l*DD2, nullptr, gckc + (size_t)l*MROWS*DDIM, 0);
        GEMM_DD(ghs, dec_cv + l*DD2, nullptr, gcvc + (size_t)l*MROWS*DDIM, 0);
    }

    // ===== full 16-iteration decode in ONE persistent kernel =====
    decode_megakernel<<<NB, NT>>>(mask, emb,
                                  dec_sq, dec_sk, dec_sv, dec_so, dec_ln1,
                                  dec_cq, dec_co, dec_ln2,
                                  dec_w1, dec_w2, dec_ln3, dec_lnf,
                                  lm, out);
}

// round 14
// speedup vs baseline: 1.0832x; 1.0832x over previous
#include <cuda_runtime.h>
#include <math.h>

#define BB   4
#define SS   64
#define DDIM 512
#define HH   8
#define DH   64
#define DFF  2048
#define LLAY 2
#define VV   32128
#define TT   16
#define NEGV (-1e9f)

#define GF_RES  1
#define GF_RELU 2

#define NB 148
#define NT 512

// ---------------- scratch (device globals; no allocations) ----------------
__device__ float g_x  [BB*SS*DDIM];
__device__ float g_h  [BB*SS*DDIM];
__device__ float g_q  [BB*SS*DDIM];
__device__ float g_k  [BB*SS*DDIM];
__device__ float g_v  [BB*SS*DDIM];
__device__ float g_at [BB*SS*DDIM];
__device__ float g_ff [BB*SS*DFF];
__device__ float g_hs [BB*SS*DDIM];
__device__ float g_ckc[LLAY*BB*SS*DDIM];
__device__ float g_cvc[LLAY*BB*SS*DDIM];
__device__ float g_skc[LLAY*BB*TT*DDIM];
__device__ float g_svc[LLAY*BB*TT*DDIM];
__device__ float g_xd [BB*DDIM];
__device__ float g_qd [BB*DDIM];
__device__ float g_ad [BB*DDIM];
__device__ float g_fd [BB*DFF];
__device__ float g_logits[BB*VV];
__device__ float g_part[1048576];
// decode k-split partial buffers: [kb(4)][m(4)][512]
__device__ float g_p3[16*DDIM];
__device__ float g_p4[16*DDIM];
__device__ float g_p6[16*DDIM];
__device__ float g_p8[16*DDIM];
// distributed softmax stats: per (batch, block)
__device__ float g_stm[BB*NB];
__device__ float g_sts[BB*NB];
__device__ int   g_sti[BB*NB];
__device__ float g_M [BB];
__device__ float g_iS[BB];

__device__ unsigned g_barcnt = 0;
__device__ unsigned g_bargen = 0;

// ======================= encoder kernels =======================
__global__ void embed_kernel(const int* __restrict__ ids, const float* __restrict__ emb) {
    int row = blockIdx.x;
    int id  = ids[row];
    for (int d = threadIdx.x; d < DDIM; d += 256)
        g_x[row*DDIM + d] = emb[(size_t)id*DDIM + d];
}

__global__ void rmsnorm_kernel(const float* __restrict__ x, const float* __restrict__ w,
                               float* __restrict__ o) {
    int r = blockIdx.x, tid = threadIdx.x;
    __shared__ float red[256];
    float a = x[r*DDIM + tid];
    float b = x[r*DDIM + 256 + tid];
    red[tid] = a*a + b*b;
    __syncthreads();
    for (int s = 128; s > 0; s >>= 1) { if (tid < s) red[tid] += red[tid+s]; __syncthreads(); }
    float inv = rsqrtf(red[0] / (float)DDIM + 1e-6f);
    o[r*DDIM + tid]       = a * inv * w[tid];
    o[r*DDIM + 256 + tid] = b * inv * w[256 + tid];
}

__global__ void gemm_split(const float* __restrict__ A, const float* __restrict__ W,
                           float* __restrict__ part, int M, int N, int K, int KS) {
    __shared__ float As[16][64];
    __shared__ float Bs[16][64];
    int row0 = blockIdx.y * 64, col0 = blockIdx.x * 64;
    int ksid = blockIdx.z;
    int kc = K / KS;
    int kbeg = ksid * kc, kend = kbeg + kc;
    int tid = threadIdx.x;
    int ty = tid / 16, tx = tid % 16;
    float acc[4][4];
    #pragma unroll
    for (int i = 0; i < 4; i++)
        #pragma unroll
        for (int j = 0; j < 4; j++) acc[i][j] = 0.f;

    for (int k0 = kbeg; k0 < kend; k0 += 16) {
        #pragma unroll
        for (int p = 0; p < 4; p++) {
            int i = tid + p*256;
            int r = i >> 4, c = i & 15;
            As[c][r] = A[(row0 + r)*K + k0 + c];
        }
        #pragma unroll
        for (int p = 0; p < 4; p++) {
            int i = tid + p*256;
            int r = i >> 6, c = i & 63;
            Bs[r][c] = W[(size_t)(k0 + r)*N + col0 + c];
        }
        __syncthreads();
        #pragma unroll
        for (int k = 0; k < 16; k++) {
            float a[4], b[4];
            #pragma unroll
            for (int i = 0; i < 4; i++) a[i] = As[k][ty*4 + i];
            #pragma unroll
            for (int j = 0; j < 4; j++) b[j] = Bs[k][tx*4 + j];
            #pragma unroll
            for (int i = 0; i < 4; i++)
                #pragma unroll
                for (int j = 0; j < 4; j++) acc[i][j] += a[i]*b[j];
        }
        __syncthreads();
    }
    float* pc = part + (size_t)ksid * M * N;
    #pragma unroll
    for (int i = 0; i < 4; i++) {
        int r = row0 + ty*4 + i;
        #pragma unroll
        for (int j = 0; j < 4; j++)
            pc[(size_t)r*N + col0 + tx*4 + j] = acc[i][j];
    }
}

__global__ void gemm_reduce(const float* __restrict__ part, const float* __restrict__ res,
                            float* __restrict__ C, int MN, int KS, int flags) {
    int i = (blockIdx.x*256 + threadIdx.x) * 4;
    if (i >= MN) return;
    float4 s = *(const float4*)(part + i);
    for (int k = 1; k < KS; k++) {
        float4 p = *(const float4*)(part + (size_t)k*MN + i);
        s.x += p.x; s.y += p.y; s.z += p.z; s.w += p.w;
    }
    if (flags & GF_RES) {
        float4 r = *(const float4*)(res + i);
        s.x += r.x; s.y += r.y; s.z += r.z; s.w += r.w;
    }
    if (flags & GF_RELU) {
        s.x = fmaxf(s.x, 0.f); s.y = fmaxf(s.y, 0.f);
        s.z = fmaxf(s.z, 0.f); s.w = fmaxf(s.w, 0.f);
    }
    *(float4*)(C + i) = s;
}

__global__ void enc_attn(const float* __restrict__ Q, const float* __restrict__ K,
                         const float* __restrict__ V, const float* __restrict__ mask,
                         float* __restrict__ O) {
    int bh = blockIdx.x; int b = bh >> 3, h = bh & 7;
    int tid = threadIdx.x;
    __shared__ float Ks[64*65], Vs[64*65], sc[64], se[64];
    for (int i = tid; i < 4096; i += 64) {
        int r = i >> 6, c = i & 63;
        Ks[r*65 + c] = K[(size_t)(b*SS + r)*DDIM + h*DH + c];
        Vs[r*65 + c] = V[(size_t)(b*SS + r)*DDIM + h*DH + c];
    }
    __syncthreads();
    float bias = (1.f - mask[b*SS + tid]) * NEGV;
    for (int q = 0; q < SS; q++) {
        const float* qr = &Q[(size_t)(b*SS + q)*DDIM + h*DH];
        float s = 0.f;
        #pragma unroll 8
        for (int d = 0; d < DH; d++) s += qr[d]*Ks[tid*65 + d];
        sc[tid] = s * 0.125f + bias;
        __syncthreads();
        float mx = -1e30f;
        for (int j = 0; j < 64; j++) mx = fmaxf(mx, sc[j]);
        se[tid] = expf(sc[tid] - mx);
        __syncthreads();
        float den = 0.f;
        for (int j = 0; j < 64; j++) den += se[j];
        float o = 0.f;
        #pragma unroll 8
        for (int j = 0; j < 64; j++) o += se[j]*Vs[j*65 + tid];
        O[(size_t)(b*SS + q)*DDIM + h*DH + tid] = o / den;
        __syncthreads();
    }
}

// ======================= decode megakernel =======================
__shared__ float  s_xs[4*DFF];     // 32KB
__shared__ float4 s_xt[DDIM];      // 8KB
__shared__ float  s_red[1104];
__shared__ float  s_sinv[4];
__shared__ float  s_sc[64];
__shared__ float  s_se[64];
__shared__ float  s_q [64];
__shared__ float  s_wm[64];        // per-warp softmax stats [w][b]
__shared__ float  s_ws[64];
__shared__ int    s_wi[64];

__device__ __forceinline__ void gridbar() {
    __syncthreads();
    if (threadIdx.x == 0) {
        __threadfence();
        unsigned my = *(volatile unsigned*)&g_bargen;
        unsigned a = atomicAdd(&g_barcnt, 1u);
        if (a == gridDim.x - 1) {
            atomicExch(&g_barcnt, 0u);
            __threadfence();
            *(volatile unsigned*)&g_bargen = my + 1u;
        } else {
            while (*(volatile unsigned*)&g_bargen == my) { }
            __threadfence();
        }
    }
    __syncthreads();
}

// online-softmax merge: (m,s,i) <- merge((m,s,i),(m2,s2,i2)); argmax keeps min index on ties
__device__ __forceinline__ void smerge(float& m, float& s, int& i,
                                       float m2, float s2, int i2) {
    float mm = fmaxf(m, m2);
    s = s*expf(m - mm) + s2*expf(m2 - mm);
    if (m2 > m || (m2 == m && i2 < i)) i = i2;
    m = mm;
}

// K=512 prep with optional partial-sum input P[kb(4)][m(4)][512] added to base x.
__device__ __forceinline__ void prep512p(const float* __restrict__ x,
                                         const float* __restrict__ P,
                                         const float* __restrict__ ln, bool xt) {
    int tid = threadIdx.x, lane = tid & 31, w = tid >> 5;
    float v0 = x[tid], v1 = x[512 + tid], v2 = x[1024 + tid], v3 = x[1536 + tid];
    if (P) {
        #pragma unroll
        for (int kb = 0; kb < 4; kb++) {
            v0 += P[(kb*4+0)*512 + tid];
            v1 += P[(kb*4+1)*512 + tid];
            v2 += P[(kb*4+2)*512 + tid];
            v3 += P[(kb*4+3)*512 + tid];
        }
    }
    if (ln) {
        float s0 = v0*v0, s1 = v1*v1, s2 = v2*v2, s3 = v3*v3;
        #pragma unroll
        for (int off = 16; off > 0; off >>= 1) {
            s0 += __shfl_xor_sync(0xffffffffu, s0, off);
            s1 += __shfl_xor_sync(0xffffffffu, s1, off);
            s2 += __shfl_xor_sync(0xffffffffu, s2, off);
            s3 += __shfl_xor_sync(0xffffffffu, s3, off);
        }
        if (lane == 0) {
            s_red[w] = s0; s_red[16 + w] = s1; s_red[32 + w] = s2; s_red[48 + w] = s3;
        }
        float lw = ln[tid];
        v0 *= lw; v1 *= lw; v2 *= lw; v3 *= lw;
    }
    s_xs[tid] = v0; s_xs[512 + tid] = v1; s_xs[1024 + tid] = v2; s_xs[1536 + tid] = v3;
    if (xt) s_xt[tid] = make_float4(v0, v1, v2, v3);
    __syncthreads();
    if (ln && tid < 4) {
        float s = 0.f;
        #pragma unroll
        for (int ww = 0; ww < 16; ww++) s += s_red[tid*16 + ww];
        s_sinv[tid] = rsqrtf(s / 512.0f + 1e-6f);
    }
    __syncthreads();
}

__device__ __forceinline__ void materialize_x(const float* __restrict__ P, int m) {
    int tid = threadIdx.x;
    float v = g_xd[m*512 + tid];
    #pragma unroll
    for (int kb = 0; kb < 4; kb++) v += P[(kb*4+m)*512 + tid];
    g_xd[m*512 + tid] = v;
}

__device__ __forceinline__ void prep_relu2048(const float* __restrict__ x) {
    const float4* xf = (const float4*)x;
    float4* sf = (float4*)s_xs;
    #pragma unroll
    for (int i = threadIdx.x; i < 2048; i += NT) {
        float4 p = xf[i];
        p.x = fmaxf(p.x, 0.f); p.y = fmaxf(p.y, 0.f);
        p.z = fmaxf(p.z, 0.f); p.w = fmaxf(p.w, 0.f);
        sf[i] = p;
    }
    __syncthreads();
}

template<int K>
__device__ __forceinline__ void gemv_tile(const float* __restrict__ W, int N, int tile,
                                          float* __restrict__ dst, int mstride,
                                          bool use_sinv) {
    constexpr int KC = K / 32;
    int tid = threadIdx.x;
    int w = tid >> 5, lane = tid & 31;
    int sub = lane >> 4, c = lane & 15;
    int ks = w*2 + sub;
    int col = tile*16 + c;
    const float* xp = s_xs + ks*KC;
    const float* wp = W + (size_t)(ks*KC)*N + col;
    float a0=0.f, a1=0.f, a2=0.f, a3=0.f;
    for (int k0 = 0; k0 < KC; k0 += 16) {
        #pragma unroll
        for (int k = 0; k < 16; k++) {
            float wv = wp[(size_t)(k0+k)*N];
            a0 += xp[k0+k]*wv; a1 += xp[K+k0+k]*wv;
            a2 += xp[2*K+k0+k]*wv; a3 += xp[3*K+k0+k]*wv;
        }
    }
    a0 += __shfl_xor_sync(0xffffffffu, a0, 16);
    a1 += __shfl_xor_sync(0xffffffffu, a1, 16);
    a2 += __shfl_xor_sync(0xffffffffu, a2, 16);
    a3 += __shfl_xor_sync(0xffffffffu, a3, 16);
    if (sub == 0) {
        s_red[(c*4+0)*17 + w] = a0;
        s_red[(c*4+1)*17 + w] = a1;
        s_red[(c*4+2)*17 + w] = a2;
        s_red[(c*4+3)*17 + w] = a3;
    }
    __syncthreads();
    if (tid < 64) {
        float s = 0.f;
        #pragma unroll
        for (int w2 = 0; w2 < 16; w2++) s += s_red[tid*17 + w2];
        int cc = tid >> 2, m = tid & 3;
        int oc = tile*16 + cc;
        if (use_sinv) s *= s_sinv[m];
        dst[(size_t)m*mstride + oc] = s;
    }
    __syncthreads();
}

template<int K, int KSB>
__device__ __forceinline__ void gemv_part(const float* __restrict__ W, int N, int tile, int kb,
                                          float* __restrict__ P, bool use_sinv) {
    constexpr int KB = K / KSB;
    constexpr int KC = KB / 32;
    int tid = threadIdx.x;
    int w = tid >> 5, lane = tid & 31;
    int sub = lane >> 4, c = lane & 15;
    int ks = w*2 + sub;
    int col = tile*16 + c;
    int row0 = kb*KB + ks*KC;
    const float* xp = s_xs + row0;
    const float* wp = W + (size_t)row0*N + col;
    float a0=0.f, a1=0.f, a2=0.f, a3=0.f;
    #pragma unroll
    for (int k = 0; k < KC; k++) {
        float wv = wp[(size_t)k*N];
        a0 += xp[k]*wv; a1 += xp[K+k]*wv; a2 += xp[2*K+k]*wv; a3 += xp[3*K+k]*wv;
    }
    a0 += __shfl_xor_sync(0xffffffffu, a0, 16);
    a1 += __shfl_xor_sync(0xffffffffu, a1, 16);
    a2 += __shfl_xor_sync(0xffffffffu, a2, 16);
    a3 += __shfl_xor_sync(0xffffffffu, a3, 16);
    if (sub == 0) {
        s_red[(c*4+0)*17 + w] = a0;
        s_red[(c*4+1)*17 + w] = a1;
        s_red[(c*4+2)*17 + w] = a2;
        s_red[(c*4+3)*17 + w] = a3;
    }
    __syncthreads();
    if (tid < 64) {
        float s = 0.f;
        #pragma unroll
        for (int w2 = 0; w2 < 16; w2++) s += s_red[tid*17 + w2];
        int cc = tid >> 2, m = tid & 3;
        int oc = tile*16 + cc;
        if (use_sinv) s *= s_sinv[m];
        P[(size_t)(kb*4+m)*N + oc] = s;
    }
    __syncthreads();
}

// warp-per-tile logits with fused per-block softmax stats (online max/sum/argmax)
__device__ __forceinline__ void logits_warp_stats(const float* __restrict__ lm,
                                                  float* __restrict__ dst) {
    int tid = threadIdx.x;
    int lane = tid & 31, w = tid >> 5;
    int gw = blockIdx.x * (NT/32) + w;
    float si0 = s_sinv[0], si1 = s_sinv[1], si2 = s_sinv[2], si3 = s_sinv[3];
    int sub = lane >> 4, c = lane & 15;
    float stm0=-1e30f, stm1=-1e30f, stm2=-1e30f, stm3=-1e30f;
    float sts0=0.f, sts1=0.f, sts2=0.f, sts3=0.f;
    int   sti0=0, sti1=0, sti2=0, sti3=0;
    const int NTILE = VV / 16;
    for (int tile = gw; tile < NTILE; tile += NB*(NT/32)) {
        int col = tile*16 + c;
        const float4* xp = s_xt + sub*256;
        const float*  wp = lm + (size_t)(sub*256)*VV + col;
        float a0=0.f, a1=0.f, a2=0.f, a3=0.f;
        for (int k0 = 0; k0 < 256; k0 += 32) {
            float wv[32];
            #pragma unroll
            for (int k = 0; k < 32; k++) wv[k] = wp[(size_t)(k0+k)*VV];
            #pragma unroll
            for (int k = 0; k < 32; k++) {
                float4 x4 = xp[k0+k];
                a0 += x4.x*wv[k]; a1 += x4.y*wv[k]; a2 += x4.z*wv[k]; a3 += x4.w*wv[k];
            }
        }
        a0 += __shfl_xor_sync(0xffffffffu, a0, 16);
        a1 += __shfl_xor_sync(0xffffffffu, a1, 16);
        a2 += __shfl_xor_sync(0xffffffffu, a2, 16);
        a3 += __shfl_xor_sync(0xffffffffu, a3, 16);
        if (sub == 0) {
            float v0 = a0*si0, v1 = a1*si1, v2 = a2*si2, v3 = a3*si3;
            dst[(size_t)0*VV + col] = v0;
            dst[(size_t)1*VV + col] = v1;
            dst[(size_t)2*VV + col] = v2;
            dst[(size_t)3*VV + col] = v3;
            stm0 = v0; sts0 = 1.f; sti0 = col;
            stm1 = v1; sts1 = 1.f; sti1 = col;
            stm2 = v2; sts2 = 1.f; sti2 = col;
            stm3 = v3; sts3 = 1.f; sti3 = col;
        }
    }
    // warp butterfly merge of stats
    #pragma unroll
    for (int off = 16; off > 0; off >>= 1) {
        float m2, s2; int i2;
        m2 = __shfl_xor_sync(0xffffffffu, stm0, off); s2 = __shfl_xor_sync(0xffffffffu, sts0, off);
        i2 = __shfl_xor_sync(0xffffffffu, sti0, off); smerge(stm0, sts0, sti0, m2, s2, i2);
        m2 = __shfl_xor_sync(0xffffffffu, stm1, off); s2 = __shfl_xor_sync(0xffffffffu, sts1, off);
        i2 = __shfl_xor_sync(0xffffffffu, sti1, off); smerge(stm1, sts1, sti1, m2, s2, i2);
        m2 = __shfl_xor_sync(0xffffffffu, stm2, off); s2 = __shfl_xor_sync(0xffffffffu, sts2, off);
        i2 = __shfl_xor_sync(0xffffffffu, sti2, off); smerge(stm2, sts2, sti2, m2, s2, i2);
        m2 = __shfl_xor_sync(0xffffffffu, stm3, off); s2 = __shfl_xor_sync(0xffffffffu, sts3, off);
        i2 = __shfl_xor_sync(0xffffffffu, sti3, off); smerge(stm3, sts3, sti3, m2, s2, i2);
    }
    if (lane == 0) {
        s_wm[w*4+0] = stm0; s_ws[w*4+0] = sts0; s_wi[w*4+0] = sti0;
        s_wm[w*4+1] = stm1; s_ws[w*4+1] = sts1; s_wi[w*4+1] = sti1;
        s_wm[w*4+2] = stm2; s_ws[w*4+2] = sts2; s_wi[w*4+2] = sti2;
        s_wm[w*4+3] = stm3; s_ws[w*4+3] = sts3; s_wi[w*4+3] = sti3;
    }
    __syncthreads();
    if (tid < 4) {
        int b = tid;
        float m = s_wm[b], s = s_ws[b]; int i = s_wi[b];
        for (int ww = 1; ww < 16; ww++)
            smerge(m, s, i, s_wm[ww*4+b], s_ws[ww*4+b], s_wi[ww*4+b]);
        g_stm[b*NB + blockIdx.x] = m;
        g_sts[b*NB + blockIdx.x] = s;
        g_sti[b*NB + blockIdx.x] = i;
    }
    __syncthreads();
}

__global__ void __launch_bounds__(NT, 1)
decode_megakernel(const float* __restrict__ mask, const float* __restrict__ emb,
                  const float* __restrict__ sq, const float* __restrict__ sk,
                  const float* __restrict__ sv, const float* __restrict__ so,
                  const float* __restrict__ ln1, const float* __restrict__ cq,
                  const float* __restrict__ co, const float* __restrict__ ln2,
                  const float* __restrict__ w1, const float* __restrict__ w2,
                  const float* __restrict__ ln3, const float* __restrict__ lnf,
                  const float* __restrict__ lm, float* __restrict__ out) {
    const size_t DD2 = (size_t)DDIM*DDIM;
    const size_t DF  = (size_t)DDIM*DFF;
    int tid = threadIdx.x;
    int bid = blockIdx.x;

    if (bid < 4)
        g_xd[bid*DDIM + tid] = emb[tid];
    gridbar();

    for (int t = 0; t < TT; t++) {
        for (int l = 0; l < LLAY; l++) {
            // ---- S1: rms(ln1) + QKV ----
            if (bid < 96) {
                prep512p(g_xd, (l == 1) ? g_p8 : nullptr, ln1 + l*DDIM, false);
                int seg = bid >> 5, ti = bid & 31;
                if (seg == 0) {
                    gemv_tile<DDIM>(sq + l*DD2, DDIM, ti, g_qd, DDIM, true);
                } else if (seg == 1) {
                    gemv_tile<DDIM>(sk + l*DD2, DDIM, ti,
                                    g_skc + (size_t)(l*BB*TT + t)*DDIM, TT*DDIM, true);
                } else {
                    gemv_tile<DDIM>(sv + l*DD2, DDIM, ti,
                                    g_svc + (size_t)(l*BB*TT + t)*DDIM, TT*DDIM, true);
                }
            }
            gridbar();

            // ---- S2: self-attention; l==1: blocks 32-35 materialize x += P8 ----
            if (bid < 32) {
                int b = bid >> 3, h = bid & 7;
                int nk = t + 1;
                const float* q = g_qd + b*DDIM + h*DH;
                if (tid < nk) {
                    const float* kr = g_skc + (size_t)((l*BB + b)*TT + tid)*DDIM + h*DH;
                    float s = 0.f;
                    #pragma unroll 16
                    for (int d = 0; d < DH; d++) s += q[d]*kr[d];
                    s_sc[tid] = s * 0.125f;
                }
                __syncthreads();
                if (tid < nk) {
                    float mx = -1e30f;
                    for (int j = 0; j < nk; j++) mx = fmaxf(mx, s_sc[j]);
                    s_se[tid] = expf(s_sc[tid] - mx);
                }
                __syncthreads();
                if (tid < 64) {
                    float den = 0.f, o = 0.f;
                    for (int j = 0; j < nk; j++) {
                        den += s_se[j];
                        o += s_se[j]*g_svc[(size_t)((l*BB + b)*TT + j)*DDIM + h*DH + tid];
                    }
                    g_ad[b*DDIM + h*DH + tid] = o / den;
                }
            } else if (l == 1 && bid < 36) {
                materialize_x(g_p8, bid - 32);
            }
            gridbar();

            // ---- S3: O-proj partials ----
            if (bid < 128) {
                prep512p(g_ad, nullptr, nullptr, false);
                gemv_part<DDIM, 4>(so + l*DD2, DDIM, bid & 31, bid >> 5, g_p3, false);
            }
            gridbar();

            // ---- S4: rms(ln2) over x+P3 -> cross-Q partials ----
            if (bid < 128) {
                prep512p(g_xd, g_p3, ln2 + l*DDIM, false);
                gemv_part<DDIM, 4>(cq + l*DD2, DDIM, bid & 31, bid >> 5, g_p4, true);
            }
            gridbar();

            // ---- S5: cross-attention; blocks 32-35 materialize x += P3 ----
            if (bid < 32) {
                int b = bid >> 3, h = bid & 7;
                if (tid < 64) {
                    float qq = 0.f;
                    #pragma unroll
                    for (int kb = 0; kb < 4; kb++)
                        qq += g_p4[(kb*4+b)*DDIM + h*DH + tid];
                    s_q[tid] = qq;
                }
                __syncthreads();
                if (tid < 64) {
                    const float* kr = g_ckc + (size_t)((l*BB + b)*SS + tid)*DDIM + h*DH;
                    float s = 0.f;
                    #pragma unroll 16
                    for (int d = 0; d < DH; d++) s += s_q[d]*kr[d];
                    s_sc[tid] = s * 0.125f + (1.f - mask[b*SS + tid]) * NEGV;
                }
                __syncthreads();
                if (tid < 64) {
                    float mx = -1e30f;
                    for (int j = 0; j < 64; j++) mx = fmaxf(mx, s_sc[j]);
                    s_se[tid] = expf(s_sc[tid] - mx);
                }
                __syncthreads();
                if (tid < 64) {
                    float den = 0.f, o = 0.f;
                    #pragma unroll 8
                    for (int j = 0; j < 64; j++) {
                        den += s_se[j];
                        o += s_se[j]*g_cvc[(size_t)((l*BB + b)*SS + j)*DDIM + h*DH + tid];
                    }
                    g_ad[b*DDIM + h*DH + tid] = o / den;
                }
            } else if (bid >= 32 && bid < 36) {
                materialize_x(g_p3, bid - 32);
            }
            gridbar();

            // ---- S6: cross O-proj partials ----
            if (bid < 128) {
                prep512p(g_ad, nullptr, nullptr, false);
                gemv_part<DDIM, 4>(co + l*DD2, DDIM, bid & 31, bid >> 5, g_p6, false);
            }
            gridbar();

            // ---- S7: rms(ln3) over x+P6 -> W1 direct ----
            if (bid < 128) {
                prep512p(g_xd, g_p6, ln3 + l*DDIM, false);
                gemv_tile<DDIM>(w1 + l*DF, DFF, bid, g_fd, DFF, true);
            }
            gridbar();

            // ---- S8: relu + W2 partials; blocks 128-131 materialize x += P6 ----
            if (bid < 128) {
                prep_relu2048(g_fd);
                gemv_part<DFF, 4>(w2 + l*DF, DDIM, bid & 31, bid >> 5, g_p8, false);
            } else if (bid < 132) {
                materialize_x(g_p6, bid - 128);
            }
            gridbar();
        }

        // ---- logits + fused per-block softmax stats ----
        prep512p(g_xd, g_p8, lnf, true);
        logits_warp_stats(lm, g_logits);
        gridbar();

        // ---- B: aggregate stats (4 blocks); write M, 1/S, pred; zero g_xd ----
        if (bid < 4) {
            int b = bid;
            float m = -1e30f, s = 0.f; int i = 0x7fffffff;
            if (tid < NB) { m = g_stm[b*NB + tid]; s = g_sts[b*NB + tid]; i = g_sti[b*NB + tid]; }
            float* rm = s_xs; float* rs = s_xs + 256; int* ri = (int*)(s_xs + 512);
            if (tid < 256) { rm[tid] = m; rs[tid] = s; ri[tid] = i; }
            __syncthreads();
            for (int st = 128; st > 0; st >>= 1) {
                if (tid < st) smerge(rm[tid], rs[tid], ri[tid], rm[tid+st], rs[tid+st], ri[tid+st]);
                __syncthreads();
            }
            if (tid == 0) {
                g_M[b] = rm[0];
                g_iS[b] = 1.f / rs[0];
                out[(size_t)BB*TT*VV + b*TT + t] = (ri[0] == 0) ? 1.0f : 0.0f;
            }
            g_xd[b*DDIM + tid] = 0.f;
        }
        gridbar();

        // ---- C: fused probs-write + soft embedding ----
        {
            float M0 = g_M[0], M1 = g_M[1], M2 = g_M[2], M3 = g_M[3];
            float iS0 = g_iS[0], iS1 = g_iS[1], iS2 = g_iS[2], iS3 = g_iS[3];
            float a0=0.f, a1=0.f, a2=0.f, a3=0.f;
            int d = tid;
            for (int t0 = bid; t0 < VV/128; t0 += NB) {
                int v0 = t0*128;
                __syncthreads();
                {
                    int m = tid >> 7, j = tid & 127;
                    float lg = g_logits[(size_t)m*VV + v0 + j];
                    float Mv  = (m == 0) ? M0  : (m == 1) ? M1  : (m == 2) ? M2  : M3;
                    float iSv = (m == 0) ? iS0 : (m == 1) ? iS1 : (m == 2) ? iS2 : iS3;
                    float p = expf(lg - Mv) * iSv;
                    out[(size_t)(m*TT + t)*VV + v0 + j] = p;
                    s_red[m*128 + j] = p;
                }
                __syncthreads();
                if (t + 1 < TT) {
                    for (int j0 = 0; j0 < 128; j0 += 32) {
                        float ev[32];
                        #pragma unroll
                        for (int j = 0; j < 32; j++)
                            ev[j] = emb[(size_t)(v0 + j0 + j)*DDIM + d];
                        #pragma unroll
                        for (int j = 0; j < 32; j++) {
                            a0 += s_red[j0+j]*ev[j];     a1 += s_red[128+j0+j]*ev[j];
                            a2 += s_red[256+j0+j]*ev[j]; a3 += s_red[384+j0+j]*ev[j];
                        }
                    }
                }
            }
            if (t + 1 < TT) {
                atomicAdd(&g_xd[0*DDIM + d], a0);
                atomicAdd(&g_xd[1*DDIM + d], a1);
                atomicAdd(&g_xd[2*DDIM + d], a2);
                atomicAdd(&g_xd[3*DDIM + d], a3);
            }
        }
        gridbar();
    }
}

// ---------------- launcher ----------------
extern "C" void kernel_launch(void* const* d_in, const int* in_sizes, int n_in,
                              void* d_out, int out_size) {
    const int*   ids     = (const int*)  d_in[0];
    const float* mask    = (const float*)d_in[1];
    const float* emb     = (const float*)d_in[2];
    const float* enc_wq  = (const float*)d_in[3];
    const float* enc_wk  = (const float*)d_in[4];
    const float* enc_wv  = (const float*)d_in[5];
    const float* enc_wo  = (const float*)d_in[6];
    const float* enc_ln1 = (const float*)d_in[7];
    const float* enc_w1  = (const float*)d_in[8];
    const float* enc_w2  = (const float*)d_in[9];
    const float* enc_ln2 = (const float*)d_in[10];
    const float* enc_lnf = (const float*)d_in[11];
    const float* dec_sq  = (const float*)d_in[12];
    const float* dec_sk  = (const float*)d_in[13];
    const float* dec_sv  = (const float*)d_in[14];
    const float* dec_so  = (const float*)d_in[15];
    const float* dec_ln1 = (const float*)d_in[16];
    const float* dec_cq  = (const float*)d_in[17];
    const float* dec_ck  = (const float*)d_in[18];
    const float* dec_cv  = (const float*)d_in[19];
    const float* dec_co  = (const float*)d_in[20];
    const float* dec_ln2 = (const float*)d_in[21];
    const float* dec_w1  = (const float*)d_in[22];
    const float* dec_w2  = (const float*)d_in[23];
    const float* dec_ln3 = (const float*)d_in[24];
    const float* dec_lnf = (const float*)d_in[25];
    const float* lm      = (const float*)d_in[26];
    float* out = (float*)d_out;

    float *gx, *gh, *gq, *gk, *gv, *gat, *gff, *ghs, *gckc, *gcvc, *gpart;
    cudaGetSymbolAddress((void**)&gx,   g_x);
    cudaGetSymbolAddress((void**)&gh,   g_h);
    cudaGetSymbolAddress((void**)&gq,   g_q);
    cudaGetSymbolAddress((void**)&gk,   g_k);
    cudaGetSymbolAddress((void**)&gv,   g_v);
    cudaGetSymbolAddress((void**)&gat,  g_at);
    cudaGetSymbolAddress((void**)&gff,  g_ff);
    cudaGetSymbolAddress((void**)&ghs,  g_hs);
    cudaGetSymbolAddress((void**)&gckc, g_ckc);
    cudaGetSymbolAddress((void**)&gcvc, g_cvc);
    cudaGetSymbolAddress((void**)&gpart, g_part);

    const int MROWS = BB*SS;
    const size_t DD2 = (size_t)DDIM*DDIM;
    const size_t DF  = (size_t)DDIM*DFF;
    const int MN_DD = MROWS*DDIM;
    const int MN_DF = MROWS*DFF;

    #define GEMM_DD(A, W, RES, C, FLAGS) do {                                          \
        gemm_split<<<dim3(DDIM/64, MROWS/64, 8), 256>>>(A, W, gpart, MROWS, DDIM, DDIM, 8); \
        gemm_reduce<<<MN_DD/1024, 256>>>(gpart, RES, C, MN_DD, 8, FLAGS);              \
    } while (0)

    // ===== encoder =====
    embed_kernel<<<MROWS, 256>>>(ids, emb);
    for (int l = 0; l < LLAY; l++) {
        rmsnorm_kernel<<<MROWS, 256>>>(gx, enc_ln1 + l*DDIM, gh);
        GEMM_DD(gh, enc_wq + l*DD2, nullptr, gq, 0);
        GEMM_DD(gh, enc_wk + l*DD2, nullptr, gk, 0);
        GEMM_DD(gh, enc_wv + l*DD2, nullptr, gv, 0);
        enc_attn<<<BB*HH, 64>>>(gq, gk, gv, mask, gat);
        GEMM_DD(gat, enc_wo + l*DD2, gx, gx, GF_RES);
        rmsnorm_kernel<<<MROWS, 256>>>(gx, enc_ln2 + l*DDIM, gh);
        gemm_split<<<dim3(DFF/64, MROWS/64, 2), 256>>>(gh, enc_w1 + l*DF, gpart, MROWS, DFF, DDIM, 2);
        gemm_reduce<<<MN_DF/1024, 256>>>(gpart, nullptr, gff, MN_DF, 2, GF_RELU);
        gemm_split<<<dim3(DDIM/64, MROWS/64, 8), 256>>>(gff, enc_w2 + l*DF, gpart, MROWS, DDIM, DFF, 8);
        gemm_reduce<<<MN_DD/1024, 256>>>(gpart, gx, gx, MN_DD, 8, GF_RES);
    }
    rmsnorm_kernel<<<MROWS, 256>>>(gx, enc_lnf, ghs);

    // cross K/V precompute
    for (int l = 0; l < LLAY; l++) {
        GEMM_DD(ghs, dec_ck + l*DD2, nullptr, gckc + (size_t)l*MROWS*DDIM, 0);
        GEMM_DD(ghs, dec_cv + l*DD2, nullptr, gcvc + (size_t)l*MROWS*DDIM, 0);
    }

    // ===== full 16-iteration decode in ONE persistent kernel =====
    decode_megakernel<<<NB, NT>>>(mask, emb,
                                  dec_sq, dec_sk, dec_sv, dec_so, dec_ln1,
                                  dec_cq, dec_co, dec_ln2,
                                  dec_w1, dec_w2, dec_ln3, dec_lnf,
                                  lm, out);
}

// round 16
// speedup vs baseline: 1.1669x; 1.0773x over previous
#include <cuda_runtime.h>
#include <math.h>

#define BB   4
#define SS   64
#define DDIM 512
#define HH   8
#define DH   64
#define DFF  2048
#define LLAY 2
#define VV   32128
#define TT   16
#define NEGV (-1e9f)

#define GF_RES  1
#define GF_RELU 2

#define NB 148
#define NT 512

// ---------------- scratch (device globals; no allocations) ----------------
__device__ float g_x  [BB*SS*DDIM];
__device__ float g_h  [BB*SS*DDIM];
__device__ float g_q  [BB*SS*DDIM];
__device__ float g_k  [BB*SS*DDIM];
__device__ float g_v  [BB*SS*DDIM];
__device__ float g_at [BB*SS*DDIM];
__device__ float g_ff [BB*SS*DFF];
__device__ float g_hs [BB*SS*DDIM];
__device__ float g_ckc[LLAY*BB*SS*DDIM];
__device__ float g_cvc[LLAY*BB*SS*DDIM];
__device__ float g_skc[LLAY*BB*TT*DDIM];
__device__ float g_svc[LLAY*BB*TT*DDIM];
__device__ float g_xd [BB*DDIM];
__device__ float g_qd [BB*DDIM];
__device__ float g_ad [BB*DDIM];
__device__ float g_fd [BB*DFF];
__device__ float g_logits[BB*VV];
__device__ float g_part[3145728];   // 3 weights x 8 splits x 256x512 partials
// decode k-split partial buffers: [kb(4)][m(4)][512]
__device__ float g_p3[16*DDIM];
__device__ float g_p4[16*DDIM];
__device__ float g_p6[16*DDIM];
__device__ float g_p8[16*DDIM];
// distributed softmax stats: per (batch, block)
__device__ float g_stm[BB*NB];
__device__ float g_sts[BB*NB];
__device__ int   g_sti[BB*NB];
// flag barrier state (monotonic; replay-safe)
__device__ unsigned g_flag[NB];
__device__ unsigned g_rel;
__device__ unsigned g_zflag;

// ======================= encoder kernels =======================
__global__ void embed_kernel(const int* __restrict__ ids, const float* __restrict__ emb) {
    int row = blockIdx.x;
    int id  = ids[row];
    for (int d = threadIdx.x; d < DDIM; d += 256)
        g_x[row*DDIM + d] = emb[(size_t)id*DDIM + d];
}

__global__ void rmsnorm_kernel(const float* __restrict__ x, const float* __restrict__ w,
                               float* __restrict__ o) {
    int r = blockIdx.x, tid = threadIdx.x;
    __shared__ float red[256];
    float a = x[r*DDIM + tid];
    float b = x[r*DDIM + 256 + tid];
    red[tid] = a*a + b*b;
    __syncthreads();
    for (int s = 128; s > 0; s >>= 1) { if (tid < s) red[tid] += red[tid+s]; __syncthreads(); }
    float inv = rsqrtf(red[0] / (float)DDIM + 1e-6f);
    o[r*DDIM + tid]       = a * inv * w[tid];
    o[r*DDIM + 256 + tid] = b * inv * w[256 + tid];
}

__device__ __forceinline__ void gemm_split_body(const float* __restrict__ A,
                                                const float* __restrict__ W,
                                                float* __restrict__ pc,
                                                int M, int N, int K, int kbeg, int kend) {
    __shared__ float As[16][64];
    __shared__ float Bs[16][64];
    int row0 = blockIdx.y * 64, col0 = blockIdx.x * 64;
    int tid = threadIdx.x;
    int ty = tid / 16, tx = tid % 16;
    float acc[4][4];
    #pragma unroll
    for (int i = 0; i < 4; i++)
        #pragma unroll
        for (int j = 0; j < 4; j++) acc[i][j] = 0.f;

    for (int k0 = kbeg; k0 < kend; k0 += 16) {
        #pragma unroll
        for (int p = 0; p < 4; p++) {
            int i = tid + p*256;
            int r = i >> 4, c = i & 15;
            As[c][r] = A[(row0 + r)*K + k0 + c];
        }
        #pragma unroll
        for (int p = 0; p < 4; p++) {
            int i = tid + p*256;
            int r = i >> 6, c = i & 63;
            Bs[r][c] = W[(size_t)(k0 + r)*N + col0 + c];
        }
        __syncthreads();
        #pragma unroll
        for (int k = 0; k < 16; k++) {
            float a[4], b[4];
            #pragma unroll
            for (int i = 0; i < 4; i++) a[i] = As[k][ty*4 + i];
            #pragma unroll
            for (int j = 0; j < 4; j++) b[j] = Bs[k][tx*4 + j];
            #pragma unroll
            for (int i = 0; i < 4; i++)
                #pragma unroll
                for (int j = 0; j < 4; j++) acc[i][j] += a[i]*b[j];
        }
        __syncthreads();
    }
    #pragma unroll
    for (int i = 0; i < 4; i++) {
        int r = row0 + ty*4 + i;
        #pragma unroll
        for (int j = 0; j < 4; j++)
            pc[(size_t)r*N + col0 + tx*4 + j] = acc[i][j];
    }
}

__global__ void gemm_split(const float* __restrict__ A, const float* __restrict__ W,
                           float* __restrict__ part, int M, int N, int K, int KS) {
    int ksid = blockIdx.z;
    int kc = K / KS;
    gemm_split_body(A, W, part + (size_t)ksid*M*N, M, N, K, ksid*kc, ksid*kc + kc);
}

// batched: z = wsel*KS + ksid, weights w0/w1/w2
__global__ void gemm_split3(const float* __restrict__ A, const float* __restrict__ w0,
                            const float* __restrict__ w1, const float* __restrict__ w2,
                            float* __restrict__ part, int M, int N, int K, int KS) {
    int wsel = blockIdx.z / KS, ksid = blockIdx.z % KS;
    const float* W = (wsel == 0) ? w0 : (wsel == 1) ? w1 : w2;
    int kc = K / KS;
    gemm_split_body(A, W, part + ((size_t)wsel*KS + ksid)*M*N, M, N, K, ksid*kc, ksid*kc + kc);
}

__global__ void gemm_reduce(const float* __restrict__ part, const float* __restrict__ res,
                            float* __restrict__ C, int MN, int KS, int flags) {
    int i = (blockIdx.x*256 + threadIdx.x) * 4;
    if (i >= MN) return;
    float4 s = *(const float4*)(part + i);
    for (int k = 1; k < KS; k++) {
        float4 p = *(const float4*)(part + (size_t)k*MN + i);
        s.x += p.x; s.y += p.y; s.z += p.z; s.w += p.w;
    }
    if (flags & GF_RES) {
        float4 r = *(const float4*)(res + i);
        s.x += r.x; s.y += r.y; s.z += r.z; s.w += r.w;
    }
    if (flags & GF_RELU) {
        s.x = fmaxf(s.x, 0.f); s.y = fmaxf(s.y, 0.f);
        s.z = fmaxf(s.z, 0.f); s.w = fmaxf(s.w, 0.f);
    }
    *(float4*)(C + i) = s;
}

__global__ void gemm_reduce3(const float* __restrict__ part,
                             float* __restrict__ d0, float* __restrict__ d1,
                             float* __restrict__ d2, int MN, int KS) {
    int wsel = blockIdx.y;
    float* C = (wsel == 0) ? d0 : (wsel == 1) ? d1 : d2;
    const float* p = part + (size_t)wsel*KS*MN;
    int i = (blockIdx.x*256 + threadIdx.x) * 4;
    if (i >= MN) return;
    float4 s = *(const float4*)(p + i);
    for (int k = 1; k < KS; k++) {
        float4 q = *(const float4*)(p + (size_t)k*MN + i);
        s.x += q.x; s.y += q.y; s.z += q.z; s.w += q.w;
    }
    *(float4*)(C + i) = s;
}

__global__ void enc_attn(const float* __restrict__ Q, const float* __restrict__ K,
                         const float* __restrict__ V, const float* __restrict__ mask,
                         float* __restrict__ O) {
    int bh = blockIdx.x; int b = bh >> 3, h = bh & 7;
    int tid = threadIdx.x;
    __shared__ float Ks[64*65], Vs[64*65], sc[64], se[64];
    for (int i = tid; i < 4096; i += 64) {
        int r = i >> 6, c = i & 63;
        Ks[r*65 + c] = K[(size_t)(b*SS + r)*DDIM + h*DH + c];
        Vs[r*65 + c] = V[(size_t)(b*SS + r)*DDIM + h*DH + c];
    }
    __syncthreads();
    float bias = (1.f - mask[b*SS + tid]) * NEGV;
    for (int q = 0; q < SS; q++) {
        const float* qr = &Q[(size_t)(b*SS + q)*DDIM + h*DH];
        float s = 0.f;
        #pragma unroll 8
        for (int d = 0; d < DH; d++) s += qr[d]*Ks[tid*65 + d];
        sc[tid] = s * 0.125f + bias;
        __syncthreads();
        float mx = -1e30f;
        for (int j = 0; j < 64; j++) mx = fmaxf(mx, sc[j]);
        se[tid] = expf(sc[tid] - mx);
        __syncthreads();
        float den = 0.f;
        for (int j = 0; j < 64; j++) den += se[j];
        float o = 0.f;
        #pragma unroll 8
        for (int j = 0; j < 64; j++) o += se[j]*Vs[j*65 + tid];
        O[(size_t)(b*SS + q)*DDIM + h*DH + tid] = o / den;
        __syncthreads();
    }
}

// ======================= decode megakernel =======================
__shared__ float  s_xs[4*DFF];     // 32KB
__shared__ float4 s_xt[DDIM];      // 8KB
__shared__ float  s_red[1104];
__shared__ float  s_sinv[4];
__shared__ float  s_sc[64];
__shared__ float  s_se[64];
__shared__ float  s_q [64];
__shared__ float  s_wm[64];
__shared__ float  s_ws[64];
__shared__ int    s_wi[64];
__shared__ float  s_Mg[4];
__shared__ float  s_iSg[4];
__shared__ int    s_amg[4];

// contention-free flag barrier: per-block flag words, block 0 aggregates + releases.
// Monotonic generations (seeded from persisted g_rel) => graph-replay safe, no resets.
__device__ __forceinline__ void gridbar(unsigned& gen) {
    gen++;
    __syncthreads();
    if (blockIdx.x == 0) {
        if (threadIdx.x == 0) { __threadfence(); *(volatile unsigned*)&g_flag[0] = gen; }
        if (threadIdx.x < NB)
            while (*(volatile unsigned*)&g_flag[threadIdx.x] != gen) { }
        __syncthreads();
        if (threadIdx.x == 0) { __threadfence(); *(volatile unsigned*)&g_rel = gen; }
        __syncthreads();
    } else {
        if (threadIdx.x == 0) {
            __threadfence();
            *(volatile unsigned*)&g_flag[blockIdx.x] = gen;
            while (*(volatile unsigned*)&g_rel != gen) { }
            __threadfence();   // invalidate L1 before reading peer data
        }
        __syncthreads();
    }
}

// online-softmax merge; argmax keeps min index on ties
__device__ __forceinline__ void smerge(float& m, float& s, int& i,
                                       float m2, float s2, int i2) {
    float mm = fmaxf(m, m2);
    s = s*expf(m - mm) + s2*expf(m2 - mm);
    if (m2 > m || (m2 == m && i2 < i)) i = i2;
    m = mm;
}

__device__ __forceinline__ void prep512p(const float* __restrict__ x,
                                         const float* __restrict__ P,
                                         const float* __restrict__ ln, bool xt) {
    int tid = threadIdx.x, lane = tid & 31, w = tid >> 5;
    float v0 = x[tid], v1 = x[512 + tid], v2 = x[1024 + tid], v3 = x[1536 + tid];
    if (P) {
        #pragma unroll
        for (int kb = 0; kb < 4; kb++) {
            v0 += P[(kb*4+0)*512 + tid];
            v1 += P[(kb*4+1)*512 + tid];
            v2 += P[(kb*4+2)*512 + tid];
            v3 += P[(kb*4+3)*512 + tid];
        }
    }
    if (ln) {
        float s0 = v0*v0, s1 = v1*v1, s2 = v2*v2, s3 = v3*v3;
        #pragma unroll
        for (int off = 16; off > 0; off >>= 1) {
            s0 += __shfl_xor_sync(0xffffffffu, s0, off);
            s1 += __shfl_xor_sync(0xffffffffu, s1, off);
            s2 += __shfl_xor_sync(0xffffffffu, s2, off);
            s3 += __shfl_xor_sync(0xffffffffu, s3, off);
        }
        if (lane == 0) {
            s_red[w] = s0; s_red[16 + w] = s1; s_red[32 + w] = s2; s_red[48 + w] = s3;
        }
        float lw = ln[tid];
        v0 *= lw; v1 *= lw; v2 *= lw; v3 *= lw;
    }
    s_xs[tid] = v0; s_xs[512 + tid] = v1; s_xs[1024 + tid] = v2; s_xs[1536 + tid] = v3;
    if (xt) s_xt[tid] = make_float4(v0, v1, v2, v3);
    __syncthreads();
    if (ln && tid < 4) {
        float s = 0.f;
        #pragma unroll
        for (int ww = 0; ww < 16; ww++) s += s_red[tid*16 + ww];
        s_sinv[tid] = rsqrtf(s / 512.0f + 1e-6f);
    }
    __syncthreads();
}

__device__ __forceinline__ void materialize_x(const float* __restrict__ P, int m) {
    int tid = threadIdx.x;
    float v = g_xd[m*512 + tid];
    #pragma unroll
    for (int kb = 0; kb < 4; kb++) v += P[(kb*4+m)*512 + tid];
    g_xd[m*512 + tid] = v;
}

__device__ __forceinline__ void prep_relu2048(const float* __restrict__ x) {
    const float4* xf = (const float4*)x;
    float4* sf = (float4*)s_xs;
    #pragma unroll
    for (int i = threadIdx.x; i < 2048; i += NT) {
        float4 p = xf[i];
        p.x = fmaxf(p.x, 0.f); p.y = fmaxf(p.y, 0.f);
        p.z = fmaxf(p.z, 0.f); p.w = fmaxf(p.w, 0.f);
        sf[i] = p;
    }
    __syncthreads();
}

template<int K>
__device__ __forceinline__ void gemv_tile(const float* __restrict__ W, int N, int tile,
                                          float* __restrict__ dst, int mstride,
                                          bool use_sinv) {
    constexpr int KC = K / 32;
    int tid = threadIdx.x;
    int w = tid >> 5, lane = tid & 31;
    int sub = lane >> 4, c = lane & 15;
    int ks = w*2 + sub;
    int col = tile*16 + c;
    const float* xp = s_xs + ks*KC;
    const float* wp = W + (size_t)(ks*KC)*N + col;
    float a0=0.f, a1=0.f, a2=0.f, a3=0.f;
    for (int k0 = 0; k0 < KC; k0 += 16) {
        #pragma unroll
        for (int k = 0; k < 16; k++) {
            float wv = wp[(size_t)(k0+k)*N];
            a0 += xp[k0+k]*wv; a1 += xp[K+k0+k]*wv;
            a2 += xp[2*K+k0+k]*wv; a3 += xp[3*K+k0+k]*wv;
        }
    }
    a0 += __shfl_xor_sync(0xffffffffu, a0, 16);
    a1 += __shfl_xor_sync(0xffffffffu, a1, 16);
    a2 += __shfl_xor_sync(0xffffffffu, a2, 16);
    a3 += __shfl_xor_sync(0xffffffffu, a3, 16);
    if (sub == 0) {
        s_red[(c*4+0)*17 + w] = a0;
        s_red[(c*4+1)*17 + w] = a1;
        s_red[(c*4+2)*17 + w] = a2;
        s_red[(c*4+3)*17 + w] = a3;
    }
    __syncthreads();
    if (tid < 64) {
        float s = 0.f;
        #pragma unroll
        for (int w2 = 0; w2 < 16; w2++) s += s_red[tid*17 + w2];
        int cc = tid >> 2, m = tid & 3;
        int oc = tile*16 + cc;
        if (use_sinv) s *= s_sinv[m];
        dst[(size_t)m*mstride + oc] = s;
    }
    __syncthreads();
}

template<int K, int KSB>
__device__ __forceinline__ void gemv_part(const float* __restrict__ W, int N, int tile, int kb,
                                          float* __restrict__ P, bool use_sinv) {
    constexpr int KB = K / KSB;
    constexpr int KC = KB / 32;
    int tid = threadIdx.x;
    int w = tid >> 5, lane = tid & 31;
    int sub = lane >> 4, c = lane & 15;
    int ks = w*2 + sub;
    int col = tile*16 + c;
    int row0 = kb*KB + ks*KC;
    const float* xp = s_xs + row0;
    const float* wp = W + (size_t)row0*N + col;
    float a0=0.f, a1=0.f, a2=0.f, a3=0.f;
    #pragma unroll
    for (int k = 0; k < KC; k++) {
        float wv = wp[(size_t)k*N];
        a0 += xp[k]*wv; a1 += xp[K+k]*wv; a2 += xp[2*K+k]*wv; a3 += xp[3*K+k]*wv;
    }
    a0 += __shfl_xor_sync(0xffffffffu, a0, 16);
    a1 += __shfl_xor_sync(0xffffffffu, a1, 16);
    a2 += __shfl_xor_sync(0xffffffffu, a2, 16);
    a3 += __shfl_xor_sync(0xffffffffu, a3, 16);
    if (sub == 0) {
        s_red[(c*4+0)*17 + w] = a0;
        s_red[(c*4+1)*17 + w] = a1;
        s_red[(c*4+2)*17 + w] = a2;
        s_red[(c*4+3)*17 + w] = a3;
    }
    __syncthreads();
    if (tid < 64) {
        float s = 0.f;
        #pragma unroll
        for (int w2 = 0; w2 < 16; w2++) s += s_red[tid*17 + w2];
        int cc = tid >> 2, m = tid & 3;
        int oc = tile*16 + cc;
        if (use_sinv) s *= s_sinv[m];
        P[(size_t)(kb*4+m)*N + oc] = s;
    }
    __syncthreads();
}

// warp-per-tile logits with fused per-block softmax stats
__device__ __forceinline__ void logits_warp_stats(const float* __restrict__ lm,
                                                  float* __restrict__ dst) {
    int tid = threadIdx.x;
    int lane = tid & 31, w = tid >> 5;
    int gw = blockIdx.x * (NT/32) + w;
    float si0 = s_sinv[0], si1 = s_sinv[1], si2 = s_sinv[2], si3 = s_sinv[3];
    int sub = lane >> 4, c = lane & 15;
    float stm0=-1e30f, stm1=-1e30f, stm2=-1e30f, stm3=-1e30f;
    float sts0=0.f, sts1=0.f, sts2=0.f, sts3=0.f;
    int   sti0=0, sti1=0, sti2=0, sti3=0;
    const int NTILE = VV / 16;
    for (int tile = gw; tile < NTILE; tile += NB*(NT/32)) {
        int col = tile*16 + c;
        const float4* xp = s_xt + sub*256;
        const float*  wp = lm + (size_t)(sub*256)*VV + col;
        float a0=0.f, a1=0.f, a2=0.f, a3=0.f;
        for (int k0 = 0; k0 < 256; k0 += 32) {
            float wv[32];
            #pragma unroll
            for (int k = 0; k < 32; k++) wv[k] = wp[(size_t)(k0+k)*VV];
            #pragma unroll
            for (int k = 0; k < 32; k++) {
                float4 x4 = xp[k0+k];
                a0 += x4.x*wv[k]; a1 += x4.y*wv[k]; a2 += x4.z*wv[k]; a3 += x4.w*wv[k];
            }
        }
        a0 += __shfl_xor_sync(0xffffffffu, a0, 16);
        a1 += __shfl_xor_sync(0xffffffffu, a1, 16);
        a2 += __shfl_xor_sync(0xffffffffu, a2, 16);
        a3 += __shfl_xor_sync(0xffffffffu, a3, 16);
        if (sub == 0) {
            float v0 = a0*si0, v1 = a1*si1, v2 = a2*si2, v3 = a3*si3;
            dst[(size_t)0*VV + col] = v0;
            dst[(size_t)1*VV + col] = v1;
            dst[(size_t)2*VV + col] = v2;
            dst[(size_t)3*VV + col] = v3;
            stm0 = v0; sts0 = 1.f; sti0 = col;
            stm1 = v1; sts1 = 1.f; sti1 = col;
            stm2 = v2; sts2 = 1.f; sti2 = col;
            stm3 = v3; sts3 = 1.f; sti3 = col;
        }
    }
    #pragma unroll
    for (int off = 16; off > 0; off >>= 1) {
        float m2, s2; int i2;
        m2 = __shfl_xor_sync(0xffffffffu, stm0, off); s2 = __shfl_xor_sync(0xffffffffu, sts0, off);
        i2 = __shfl_xor_sync(0xffffffffu, sti0, off); smerge(stm0, sts0, sti0, m2, s2, i2);
        m2 = __shfl_xor_sync(0xffffffffu, stm1, off); s2 = __shfl_xor_sync(0xffffffffu, sts1, off);
        i2 = __shfl_xor_sync(0xffffffffu, sti1, off); smerge(stm1, sts1, sti1, m2, s2, i2);
        m2 = __shfl_xor_sync(0xffffffffu, stm2, off); s2 = __shfl_xor_sync(0xffffffffu, sts2, off);
        i2 = __shfl_xor_sync(0xffffffffu, sti2, off); smerge(stm2, sts2, sti2, m2, s2, i2);
        m2 = __shfl_xor_sync(0xffffffffu, stm3, off); s2 = __shfl_xor_sync(0xffffffffu, sts3, off);
        i2 = __shfl_xor_sync(0xffffffffu, sti3, off); smerge(stm3, sts3, sti3, m2, s2, i2);
    }
    if (lane == 0) {
        s_wm[w*4+0] = stm0; s_ws[w*4+0] = sts0; s_wi[w*4+0] = sti0;
        s_wm[w*4+1] = stm1; s_ws[w*4+1] = sts1; s_wi[w*4+1] = sti1;
        s_wm[w*4+2] = stm2; s_ws[w*4+2] = sts2; s_wi[w*4+2] = sti2;
        s_wm[w*4+3] = stm3; s_ws[w*4+3] = sts3; s_wi[w*4+3] = sti3;
    }
    __syncthreads();
    if (tid < 4) {
        int b = tid;
        float m = s_wm[b], s = s_ws[b]; int i = s_wi[b];
        for (int ww = 1; ww < 16; ww++)
            smerge(m, s, i, s_wm[ww*4+b], s_ws[ww*4+b], s_wi[ww*4+b]);
        g_stm[b*NB + blockIdx.x] = m;
        g_sts[b*NB + blockIdx.x] = s;
        g_sti[b*NB + blockIdx.x] = i;
    }
    __syncthreads();
}

__global__ void __launch_bounds__(NT, 1)
decode_megakernel(const float* __restrict__ mask, const float* __restrict__ emb,
                  const float* __restrict__ sq, const float* __restrict__ sk,
                  const float* __restrict__ sv, const float* __restrict__ so,
                  const float* __restrict__ ln1, const float* __restrict__ cq,
                  const float* __restrict__ co, const float* __restrict__ ln2,
                  const float* __restrict__ w1, const float* __restrict__ w2,
                  const float* __restrict__ ln3, const float* __restrict__ lnf,
                  const float* __restrict__ lm, float* __restrict__ out) {
    const size_t DD2 = (size_t)DDIM*DDIM;
    const size_t DF  = (size_t)DDIM*DFF;
    int tid = threadIdx.x;
    int bid = blockIdx.x;

    // monotonic generation base (persists across graph replays)
    unsigned gen = *(volatile unsigned*)&g_rel;

    if (bid < 4)
        g_xd[bid*DDIM + tid] = emb[tid];
    gridbar(gen);

    for (int t = 0; t < TT; t++) {
        for (int l = 0; l < LLAY; l++) {
            // ---- S1: rms(ln1) + QKV ----
            if (bid < 96) {
                prep512p(g_xd, (l == 1) ? g_p8 : nullptr, ln1 + l*DDIM, false);
                int seg = bid >> 5, ti = bid & 31;
                if (seg == 0) {
                    gemv_tile<DDIM>(sq + l*DD2, DDIM, ti, g_qd, DDIM, true);
                } else if (seg == 1) {
                    gemv_tile<DDIM>(sk + l*DD2, DDIM, ti,
                                    g_skc + (size_t)(l*BB*TT + t)*DDIM, TT*DDIM, true);
                } else {
                    gemv_tile<DDIM>(sv + l*DD2, DDIM, ti,
                                    g_svc + (size_t)(l*BB*TT + t)*DDIM, TT*DDIM, true);
                }
            }
            gridbar(gen);

            // ---- S2: self-attention; l==1: blocks 32-35 materialize x += P8 ----
            if (bid < 32) {
                int b = bid >> 3, h = bid & 7;
                int nk = t + 1;
                const float* q = g_qd + b*DDIM + h*DH;
                if (tid < nk) {
                    const float* kr = g_skc + (size_t)((l*BB + b)*TT + tid)*DDIM + h*DH;
                    float s = 0.f;
                    #pragma unroll 16
                    for (int d = 0; d < DH; d++) s += q[d]*kr[d];
                    s_sc[tid] = s * 0.125f;
                }
                __syncthreads();
                if (tid < nk) {
                    float mx = -1e30f;
                    for (int j = 0; j < nk; j++) mx = fmaxf(mx, s_sc[j]);
                    s_se[tid] = expf(s_sc[tid] - mx);
                }
                __syncthreads();
                if (tid < 64) {
                    float den = 0.f, o = 0.f;
                    for (int j = 0; j < nk; j++) {
                        den += s_se[j];
                        o += s_se[j]*g_svc[(size_t)((l*BB + b)*TT + j)*DDIM + h*DH + tid];
                    }
                    g_ad[b*DDIM + h*DH + tid] = o / den;
                }
            } else if (l == 1 && bid < 36) {
                materialize_x(g_p8, bid - 32);
            }
            gridbar(gen);

            // ---- S3: O-proj partials ----
            if (bid < 128) {
                prep512p(g_ad, nullptr, nullptr, false);
                gemv_part<DDIM, 4>(so + l*DD2, DDIM, bid & 31, bid >> 5, g_p3, false);
            }
            gridbar(gen);

            // ---- S4: rms(ln2) over x+P3 -> cross-Q partials ----
            if (bid < 128) {
                prep512p(g_xd, g_p3, ln2 + l*DDIM, false);
                gemv_part<DDIM, 4>(cq + l*DD2, DDIM, bid & 31, bid >> 5, g_p4, true);
            }
            gridbar(gen);

            // ---- S5: cross-attention; blocks 32-35 materialize x += P3 ----
            if (bid < 32) {
                int b = bid >> 3, h = bid & 7;
                if (tid < 64) {
                    float qq = 0.f;
                    #pragma unroll
                    for (int kb = 0; kb < 4; kb++)
                        qq += g_p4[(kb*4+b)*DDIM + h*DH + tid];
                    s_q[tid] = qq;
                }
                __syncthreads();
                if (tid < 64) {
                    const float* kr = g_ckc + (size_t)((l*BB + b)*SS + tid)*DDIM + h*DH;
                    float s = 0.f;
                    #pragma unroll 16
                    for (int d = 0; d < DH; d++) s += s_q[d]*kr[d];
                    s_sc[tid] = s * 0.125f + (1.f - mask[b*SS + tid]) * NEGV;
                }
                __syncthreads();
                if (tid < 64) {
                    float mx = -1e30f;
                    for (int j = 0; j < 64; j++) mx = fmaxf(mx, s_sc[j]);
                    s_se[tid] = expf(s_sc[tid] - mx);
                }
                __syncthreads();
                if (tid < 64) {
                    float den = 0.f, o = 0.f;
                    #pragma unroll 8
                    for (int j = 0; j < 64; j++) {
                        den += s_se[j];
                        o += s_se[j]*g_cvc[(size_t)((l*BB + b)*SS + j)*DDIM + h*DH + tid];
                    }
                    g_ad[b*DDIM + h*DH + tid] = o / den;
                }
            } else if (bid >= 32 && bid < 36) {
                materialize_x(g_p3, bid - 32);
            }
            gridbar(gen);

            // ---- S6: cross O-proj partials ----
            if (bid < 128) {
                prep512p(g_ad, nullptr, nullptr, false);
                gemv_part<DDIM, 4>(co + l*DD2, DDIM, bid & 31, bid >> 5, g_p6, false);
            }
            gridbar(gen);

            // ---- S7: rms(ln3) over x+P6 -> W1 direct ----
            if (bid < 128) {
                prep512p(g_xd, g_p6, ln3 + l*DDIM, false);
                gemv_tile<DDIM>(w1 + l*DF, DFF, bid, g_fd, DFF, true);
            }
            gridbar(gen);

            // ---- S8: relu + W2 partials; blocks 128-131 materialize x += P6 ----
            if (bid < 128) {
                prep_relu2048(g_fd);
                gemv_part<DFF, 4>(w2 + l*DF, DDIM, bid & 31, bid >> 5, g_p8, false);
            } else if (bid < 132) {
                materialize_x(g_p6, bid - 128);
            }
            gridbar(gen);
        }

        // ---- logits + fused per-block softmax stats ----
        prep512p(g_xd, g_p8, lnf, true);
        logits_warp_stats(lm, g_logits);
        gridbar(gen);

        // ---- C (merged): redundant stat aggregate + probs + yemb + zero/pred ----
        {
            int w = tid >> 5, lane = tid & 31;
            if (w < 4) {
                float m = -1e30f, s = 0.f; int i = 0x7fffffff;
                for (int j = lane; j < NB; j += 32)
                    smerge(m, s, i, g_stm[w*NB + j], g_sts[w*NB + j], g_sti[w*NB + j]);
                #pragma unroll
                for (int off = 16; off > 0; off >>= 1) {
                    float m2 = __shfl_xor_sync(0xffffffffu, m, off);
                    float s2 = __shfl_xor_sync(0xffffffffu, s, off);
                    int   i2 = __shfl_xor_sync(0xffffffffu, i, off);
                    smerge(m, s, i, m2, s2, i2);
                }
                if (lane == 0) { s_Mg[w] = m; s_iSg[w] = 1.f/s; s_amg[w] = i; }
            }
            __syncthreads();
            if (bid == 0) {
                // zero residual accumulator + publish zero-flag + write preds
                #pragma unroll
                for (int p = 0; p < 4; p++) g_xd[p*512 + tid] = 0.f;
                __syncthreads();
                if (tid == 0) { __threadfence(); *(volatile unsigned*)&g_zflag = gen; }
                if (tid < 4)
                    out[(size_t)BB*TT*VV + tid*TT + t] = (s_amg[tid] == 0) ? 1.0f : 0.0f;
            }
            float M0 = s_Mg[0], M1 = s_Mg[1], M2 = s_Mg[2], M3 = s_Mg[3];
            float iS0 = s_iSg[0], iS1 = s_iSg[1], iS2 = s_iSg[2], iS3 = s_iSg[3];
            float a0=0.f, a1=0.f, a2=0.f, a3=0.f;
            int d = tid;
            for (int t0 = bid; t0 < VV/128; t0 += NB) {
                int v0 = t0*128;
                __syncthreads();
                {
                    int m = tid >> 7, j = tid & 127;
                    float lg = g_logits[(size_t)m*VV + v0 + j];
                    float Mv  = (m == 0) ? M0  : (m == 1) ? M1  : (m == 2) ? M2  : M3;
                    float iSv = (m == 0) ? iS0 : (m == 1) ? iS1 : (m == 2) ? iS2 : iS3;
                    float p = expf(lg - Mv) * iSv;
                    out[(size_t)(m*TT + t)*VV + v0 + j] = p;
                    s_red[m*128 + j] = p;
                }
                __syncthreads();
                if (t + 1 < TT) {
                    for (int j0 = 0; j0 < 128; j0 += 32) {
                        float ev[32];
                        #pragma unroll
                        for (int j = 0; j < 32; j++)
                            ev[j] = emb[(size_t)(v0 + j0 + j)*DDIM + d];
                        #pragma unroll
                        for (int j = 0; j < 32; j++) {
                            a0 += s_red[j0+j]*ev[j];     a1 += s_red[128+j0+j]*ev[j];
                            a2 += s_red[256+j0+j]*ev[j]; a3 += s_red[384+j0+j]*ev[j];
                        }
                    }
                }
            }
            if (t + 1 < TT) {
                if (tid == 0) { while (*(volatile unsigned*)&g_zflag < gen) { } }
                __syncthreads();
                atomicAdd(&g_xd[0*DDIM + d], a0);
                atomicAdd(&g_xd[1*DDIM + d], a1);
                atomicAdd(&g_xd[2*DDIM + d], a2);
                atomicAdd(&g_xd[3*DDIM + d], a3);
            }
        }
        gridbar(gen);
    }
}

// ---------------- launcher ----------------
extern "C" void kernel_launch(void* const* d_in, const int* in_sizes, int n_in,
                              void* d_out, int out_size) {
    const int*   ids     = (const int*)  d_in[0];
    const float* mask    = (const float*)d_in[1];
    const float* emb     = (const float*)d_in[2];
    const float* enc_wq  = (const float*)d_in[3];
    const float* enc_wk  = (const float*)d_in[4];
    const float* enc_wv  = (const float*)d_in[5];
    const float* enc_wo  = (const float*)d_in[6];
    const float* enc_ln1 = (const float*)d_in[7];
    const float* enc_w1  = (const float*)d_in[8];
    const float* enc_w2  = (const float*)d_in[9];
    const float* enc_ln2 = (const float*)d_in[10];
    const float* enc_lnf = (const float*)d_in[11];
    const float* dec_sq  = (const float*)d_in[12];
    const float* dec_sk  = (const float*)d_in[13];
    const float* dec_sv  = (const float*)d_in[14];
    const float* dec_so  = (const float*)d_in[15];
    const float* dec_ln1 = (const float*)d_in[16];
    const float* dec_cq  = (const float*)d_in[17];
    const float* dec_ck  = (const float*)d_in[18];
    const float* dec_cv  = (const float*)d_in[19];
    const float* dec_co  = (const float*)d_in[20];
    const float* dec_ln2 = (const float*)d_in[21];
    const float* dec_w1  = (const float*)d_in[22];
    const float* dec_w2  = (const float*)d_in[23];
    const float* dec_ln3 = (const float*)d_in[24];
    const float* dec_lnf = (const float*)d_in[25];
    const float* lm      = (const float*)d_in[26];
    float* out = (float*)d_out;

    float *gx, *gh, *gq, *gk, *gv, *gat, *gff, *ghs, *gckc, *gcvc, *gpart;
    cudaGetSymbolAddress((void**)&gx,   g_x);
    cudaGetSymbolAddress((void**)&gh,   g_h);
    cudaGetSymbolAddress((void**)&gq,   g_q);
    cudaGetSymbolAddress((void**)&gk,   g_k);
    cudaGetSymbolAddress((void**)&gv,   g_v);
    cudaGetSymbolAddress((void**)&gat,  g_at);
    cudaGetSymbolAddress((void**)&gff,  g_ff);
    cudaGetSymbolAddress((void**)&ghs,  g_hs);
    cudaGetSymbolAddress((void**)&gckc, g_ckc);
    cudaGetSymbolAddress((void**)&gcvc, g_cvc);
    cudaGetSymbolAddress((void**)&gpart, g_part);

    const int MROWS = BB*SS;
    const size_t DD2 = (size_t)DDIM*DDIM;
    const size_t DF  = (size_t)DDIM*DFF;
    const int MN_DD = MROWS*DDIM;
    const int MN_DF = MROWS*DFF;

    #define GEMM_DD(A, W, RES, C, FLAGS) do {                                          \
        gemm_split<<<dim3(DDIM/64, MROWS/64, 8), 256>>>(A, W, gpart, MROWS, DDIM, DDIM, 8); \
        gemm_reduce<<<MN_DD/1024, 256>>>(gpart, RES, C, MN_DD, 8, FLAGS);              \
    } while (0)

    // ===== encoder =====
    embed_kernel<<<MROWS, 256>>>(ids, emb);
    for (int l = 0; l < LLAY; l++) {
        rmsnorm_kernel<<<MROWS, 256>>>(gx, enc_ln1 + l*DDIM, gh);
        // QKV in one batched launch (3 weights x 8 k-splits = 768 blocks)
        gemm_split3<<<dim3(DDIM/64, MROWS/64, 24), 256>>>(
            gh, enc_wq + l*DD2, enc_wk + l*DD2, enc_wv + l*DD2,
            gpart, MROWS, DDIM, DDIM, 8);
        gemm_reduce3<<<dim3(MN_DD/1024, 3), 256>>>(gpart, gq, gk, gv, MN_DD, 8);
        enc_attn<<<BB*HH, 64>>>(gq, gk, gv, mask, gat);
        GEMM_DD(gat, enc_wo + l*DD2, gx, gx, GF_RES);
        rmsnorm_kernel<<<MROWS, 256>>>(gx, enc_ln2 + l*DDIM, gh);
        gemm_split<<<dim3(DFF/64, MROWS/64, 2), 256>>>(gh, enc_w1 + l*DF, gpart, MROWS, DFF, DDIM, 2);
        gemm_reduce<<<MN_DF/1024, 256>>>(gpart, nullptr, gff, MN_DF, 2, GF_RELU);
        gemm_split<<<dim3(DDIM/64, MROWS/64, 8), 256>>>(gff, enc_w2 + l*DF, gpart, MROWS, DDIM, DFF, 8);
        gemm_reduce<<<MN_DD/1024, 256>>>(gpart, gx, gx, MN_DD, 8, GF_RES);
    }
    rmsnorm_kernel<<<MROWS, 256>>>(gx, enc_lnf, ghs);

    // cross K/V precompute (batched: 2 weights x 8 splits per layer)
    for (int l = 0; l < LLAY; l++) {
        gemm_split3<<<dim3(DDIM/64, MROWS/64, 16), 256>>>(
            ghs, dec_ck + l*DD2, dec_cv + l*DD2, dec_cv + l*DD2,
            gpart, MROWS, DDIM, DDIM, 8);
        gemm_reduce3<<<dim3(MN_DD/1024, 2), 256>>>(
            gpart, gckc + (size_t)l*MROWS*DDIM, gcvc + (size_t)l*MROWS*DDIM,
            gcvc + (size_t)l*MROWS*DDIM, MN_DD, 8);
    }

    // ===== full 16-iteration decode in ONE persistent kernel =====
    decode_megakernel<<<NB, NT>>>(mask, emb,
                                  dec_sq, dec_sk, dec_sv, dec_so, dec_ln1,
                                  dec_cq, dec_co, dec_ln2,
                                  dec_w1, dec_w2, dec_ln3, dec_lnf,
                                  lm, out);
}